// round 3
// baseline (speedup 1.0000x reference)
#include <cuda_runtime.h>
#include <math.h>

// ---------------------------------------------------------------------------
// Problem constants (fixed shapes per reference)
// ---------------------------------------------------------------------------
#define BATCH   16
#define SEQ     512
#define S_IN    384
#define WDIM    1024
#define HEADS   16
#define DH      64
#define DFFDIM  4096
#define NTOP    50
#define NGRP    7
#define MTOT    (BATCH*SEQ)          // 8192 rows

// ---------------------------------------------------------------------------
// Scratch (static device globals — no dynamic allocation allowed)
// ---------------------------------------------------------------------------
__device__ float g_qkv[(size_t)MTOT * 3 * WDIM];    // 96 MB
__device__ float g_ctx[(size_t)MTOT * WDIM];        // 32 MB
__device__ float g_tmp[(size_t)MTOT * WDIM];        // 32 MB
__device__ float g_y[(size_t)MTOT * WDIM];          // 32 MB
__device__ float g_ff[(size_t)MTOT * DFFDIM];       // 128 MB
__device__ float g_hidden[(size_t)MTOT * WDIM];     // 32 MB
__device__ float g_ue[(size_t)BATCH * NGRP * WDIM]; // tiny

__device__ __forceinline__ float gelu_exact(float x) {
    return 0.5f * x * (1.0f + erff(x * 0.70710678118654752f));
}

// ---------------------------------------------------------------------------
// GEMM: C[M,N] = A[M,K] @ B[N,K]^T + bias[N]   (optionally GELU epilogue)
// 64x64 tile, BK=16, 256 threads, 4x4 micro-tile.
// ---------------------------------------------------------------------------
template<int DO_GELU>
__global__ void __launch_bounds__(256, 2) gemm_nt(
    const float* __restrict__ A, const float* __restrict__ B,
    const float* __restrict__ bias, float* __restrict__ C,
    int M, int N, int K)
{
    __shared__ float As[16][64];   // [k][m]
    __shared__ float Bs[16][64];   // [k][n]
    const int tid = threadIdx.x;
    const int tx = tid & 15, ty = tid >> 4;
    const int m0 = blockIdx.y << 6, n0 = blockIdx.x << 6;
    const int lr = tid >> 2;            // 0..63
    const int lc = (tid & 3) << 2;      // 0,4,8,12
    const float* Ap = A + (size_t)(m0 + lr) * K + lc;
    const float* Bp = B + (size_t)(n0 + lr) * K + lc;
    float acc[4][4] = {};

    for (int k0 = 0; k0 < K; k0 += 16) {
        float4 av = *(const float4*)(Ap + k0);
        float4 bv = *(const float4*)(Bp + k0);
        __syncthreads();
        As[lc + 0][lr] = av.x; As[lc + 1][lr] = av.y;
        As[lc + 2][lr] = av.z; As[lc + 3][lr] = av.w;
        Bs[lc + 0][lr] = bv.x; Bs[lc + 1][lr] = bv.y;
        Bs[lc + 2][lr] = bv.z; Bs[lc + 3][lr] = bv.w;
        __syncthreads();
        #pragma unroll
        for (int kk = 0; kk < 16; kk++) {
            float4 a = *(const float4*)&As[kk][ty << 2];
            float4 b = *(const float4*)&Bs[kk][tx << 2];
            acc[0][0] += a.x * b.x; acc[0][1] += a.x * b.y;
            acc[0][2] += a.x * b.z; acc[0][3] += a.x * b.w;
            acc[1][0] += a.y * b.x; acc[1][1] += a.y * b.y;
            acc[1][2] += a.y * b.z; acc[1][3] += a.y * b.w;
            acc[2][0] += a.z * b.x; acc[2][1] += a.z * b.y;
            acc[2][2] += a.z * b.z; acc[2][3] += a.z * b.w;
            acc[3][0] += a.w * b.x; acc[3][1] += a.w * b.y;
            acc[3][2] += a.w * b.z; acc[3][3] += a.w * b.w;
        }
    }

    const int nc = n0 + (tx << 2);
    float b0 = bias[nc + 0], b1 = bias[nc + 1], b2 = bias[nc + 2], b3 = bias[nc + 3];
    #pragma unroll
    for (int i = 0; i < 4; i++) {
        float4 o;
        o.x = acc[i][0] + b0; o.y = acc[i][1] + b1;
        o.z = acc[i][2] + b2; o.w = acc[i][3] + b3;
        if (DO_GELU) {
            o.x = gelu_exact(o.x); o.y = gelu_exact(o.y);
            o.z = gelu_exact(o.z); o.w = gelu_exact(o.w);
        }
        *(float4*)(C + (size_t)(m0 + (ty << 2) + i) * N + nc) = o;
    }
}

// ---------------------------------------------------------------------------
// Flash attention (fp32). One block per (b, h, 64-query tile). 256 threads.
// Online softmax; P staged through smem transposed for the PV GEMM.
// ---------------------------------------------------------------------------
#define ATT_STRIDE 68
#define ATT_SMEM (4 * 64 * ATT_STRIDE * 4)

__global__ void __launch_bounds__(256) attn_flash(
    const float* __restrict__ qkv, float* __restrict__ ctx)
{
    extern __shared__ float sm[];
    float* Qs = sm;                        // [d][q]
    float* Ks = sm + 64 * ATT_STRIDE;      // [d][kc]
    float* Vs = sm + 2 * 64 * ATT_STRIDE;  // [kr][d]
    float* Ps = sm + 3 * 64 * ATT_STRIDE;  // [kc][q]

    const int tid = threadIdx.x;
    const int tx = tid & 15, ty = tid >> 4;
    const int qt = blockIdx.x, h = blockIdx.y, b = blockIdx.z;
    const size_t rowbase = (size_t)b * SEQ * 3 * WDIM;
    const int hoff = h * DH;

    for (int idx = tid; idx < 64 * 64; idx += 256) {
        int qi = idx >> 6, d = idx & 63;
        Qs[d * ATT_STRIDE + qi] =
            qkv[rowbase + (size_t)(qt * 64 + qi) * 3 * WDIM + hoff + d] * 0.125f;
    }

    float m_i[4], l_i[4], O[4][4];
    #pragma unroll
    for (int i = 0; i < 4; i++) {
        m_i[i] = -1e30f; l_i[i] = 0.f;
        #pragma unroll
        for (int j = 0; j < 4; j++) O[i][j] = 0.f;
    }

    for (int kt = 0; kt < SEQ / 64; kt++) {
        __syncthreads();
        for (int idx = tid; idx < 64 * 64; idx += 256) {
            int r = idx >> 6, d = idx & 63;
            size_t base = rowbase + (size_t)(kt * 64 + r) * 3 * WDIM + hoff;
            Ks[d * ATT_STRIDE + r] = qkv[base + WDIM + d];
            Vs[r * ATT_STRIDE + d] = qkv[base + 2 * WDIM + d];
        }
        __syncthreads();

        float s[4][4] = {};
        #pragma unroll 8
        for (int d = 0; d < 64; d++) {
            float4 a = *(const float4*)&Qs[d * ATT_STRIDE + (ty << 2)];
            float4 kq = *(const float4*)&Ks[d * ATT_STRIDE + (tx << 2)];
            s[0][0] += a.x * kq.x; s[0][1] += a.x * kq.y; s[0][2] += a.x * kq.z; s[0][3] += a.x * kq.w;
            s[1][0] += a.y * kq.x; s[1][1] += a.y * kq.y; s[1][2] += a.y * kq.z; s[1][3] += a.y * kq.w;
            s[2][0] += a.z * kq.x; s[2][1] += a.z * kq.y; s[2][2] += a.z * kq.z; s[2][3] += a.z * kq.w;
            s[3][0] += a.w * kq.x; s[3][1] += a.w * kq.y; s[3][2] += a.w * kq.z; s[3][3] += a.w * kq.w;
        }

        #pragma unroll
        for (int i = 0; i < 4; i++) {
            float tmax = fmaxf(fmaxf(s[i][0], s[i][1]), fmaxf(s[i][2], s[i][3]));
            #pragma unroll
            for (int off = 8; off; off >>= 1)
                tmax = fmaxf(tmax, __shfl_xor_sync(0xffffffffu, tmax, off));
            float nm = fmaxf(m_i[i], tmax);
            float alpha = __expf(m_i[i] - nm);
            m_i[i] = nm;
            float rs = 0.f;
            #pragma unroll
            for (int j = 0; j < 4; j++) {
                float p = __expf(s[i][j] - nm);
                s[i][j] = p; rs += p;
            }
            #pragma unroll
            for (int off = 8; off; off >>= 1)
                rs += __shfl_xor_sync(0xffffffffu, rs, off);
            l_i[i] = l_i[i] * alpha + rs;
            #pragma unroll
            for (int j = 0; j < 4; j++) O[i][j] *= alpha;
        }

        #pragma unroll
        for (int i = 0; i < 4; i++)
            #pragma unroll
            for (int j = 0; j < 4; j++)
                Ps[((tx << 2) + j) * ATT_STRIDE + (ty << 2) + i] = s[i][j];
        __syncthreads();

        #pragma unroll 8
        for (int kr = 0; kr < 64; kr++) {
            float4 p = *(const float4*)&Ps[kr * ATT_STRIDE + (ty << 2)];
            float4 v = *(const float4*)&Vs[kr * ATT_STRIDE + (tx << 2)];
            O[0][0] += p.x * v.x; O[0][1] += p.x * v.y; O[0][2] += p.x * v.z; O[0][3] += p.x * v.w;
            O[1][0] += p.y * v.x; O[1][1] += p.y * v.y; O[1][2] += p.y * v.z; O[1][3] += p.y * v.w;
            O[2][0] += p.z * v.x; O[2][1] += p.z * v.y; O[2][2] += p.z * v.z; O[2][3] += p.z * v.w;
            O[3][0] += p.w * v.x; O[3][1] += p.w * v.y; O[3][2] += p.w * v.z; O[3][3] += p.w * v.w;
        }
    }

    #pragma unroll
    for (int i = 0; i < 4; i++) {
        float inv = 1.f / l_i[i];
        float4 o = { O[i][0] * inv, O[i][1] * inv, O[i][2] * inv, O[i][3] * inv };
        *(float4*)&ctx[(size_t)(b * SEQ + qt * 64 + (ty << 2) + i) * WDIM + hoff + (tx << 2)] = o;
    }
}

// ---------------------------------------------------------------------------
// Residual add + LayerNorm over W=1024. One block per row.
// ---------------------------------------------------------------------------
__global__ void __launch_bounds__(256) ln_residual(
    const float* __restrict__ x, const float* __restrict__ r,
    const float* __restrict__ gamma, const float* __restrict__ beta,
    float* __restrict__ out)
{
    __shared__ float red[2][8];
    __shared__ float stats[2];
    const int row = blockIdx.x, tid = threadIdx.x;
    const size_t base = (size_t)row * WDIM;
    float v[4];
    float s = 0.f, sq = 0.f;
    #pragma unroll
    for (int c = 0; c < 4; c++) {
        int w = tid + c * 256;
        float a = x[base + w] + r[base + w];
        v[c] = a; s += a; sq += a * a;
    }
    #pragma unroll
    for (int off = 16; off; off >>= 1) {
        s  += __shfl_xor_sync(0xffffffffu, s, off);
        sq += __shfl_xor_sync(0xffffffffu, sq, off);
    }
    int lane = tid & 31, wid = tid >> 5;
    if (lane == 0) { red[0][wid] = s; red[1][wid] = sq; }
    __syncthreads();
    if (tid == 0) {
        float ts = 0.f, tq = 0.f;
        #pragma unroll
        for (int w = 0; w < 8; w++) { ts += red[0][w]; tq += red[1][w]; }
        float mean = ts * (1.f / WDIM);
        float var  = tq * (1.f / WDIM) - mean * mean;
        stats[0] = mean;
        stats[1] = rsqrtf(var + 1e-5f);
    }
    __syncthreads();
    float mean = stats[0], rstd = stats[1];
    #pragma unroll
    for (int c = 0; c < 4; c++) {
        int w = tid + c * 256;
        out[base + w] = (v[c] - mean) * rstd * gamma[w] + beta[w];
    }
}

// ---------------------------------------------------------------------------
// Topic kernel: per (group, batch): masked max-pool over S (incl. 0),
// logits over 50 topics, softmax, ue = probs @ topic_table.
// ---------------------------------------------------------------------------
__global__ void __launch_bounds__(256) topic_kernel(
    const float* __restrict__ hidden, const int* __restrict__ in_ids,
    const int* __restrict__ res_ids, const float* __restrict__ tw,
    const float* __restrict__ tb, const float* __restrict__ tt,
    float* __restrict__ ue)
{
    __shared__ float mp[WDIM];
    __shared__ float logits[64];
    __shared__ float probs[64];
    __shared__ int sid[SEQ];
    const int tid = threadIdx.x;
    const int g = blockIdx.x, b = blockIdx.y;

    for (int s = tid; s < SEQ; s += 256) {
        int id;
        if (g < 6) id = (s < S_IN) ? in_ids[b * S_IN + s] : 0;
        else       id = (s >= S_IN) ? res_ids[b * 129 + (s - S_IN + 1)] : 0;
        sid[s] = id;
    }
    __syncthreads();

    const int gid = (g < 6) ? (g + 1) : 1;
    float acc[4] = {0.f, 0.f, 0.f, 0.f};   // max includes 0 (torch.where semantics)
    for (int s = 0; s < SEQ; s++) {
        if (sid[s] == gid) {
            const float* hr = hidden + (size_t)(b * SEQ + s) * WDIM;
            #pragma unroll
            for (int c = 0; c < 4; c++)
                acc[c] = fmaxf(acc[c], hr[tid + c * 256]);
        }
    }
    #pragma unroll
    for (int c = 0; c < 4; c++) mp[tid + c * 256] = acc[c];
    __syncthreads();

    // logits: 8 warps, topics strided by 8
    int lane = tid & 31, wid = tid >> 5;
    for (int t = wid; t < NTOP; t += 8) {
        const float* wrow = tw + (size_t)t * WDIM;
        float d = 0.f;
        for (int w = lane; w < WDIM; w += 32) d += mp[w] * wrow[w];
        #pragma unroll
        for (int off = 16; off; off >>= 1)
            d += __shfl_xor_sync(0xffffffffu, d, off);
        if (lane == 0) logits[t] = d + tb[t];
    }
    __syncthreads();

    if (tid < 32) {
        float mval = -1e30f;
        for (int t = tid; t < NTOP; t += 32) mval = fmaxf(mval, logits[t]);
        #pragma unroll
        for (int off = 16; off; off >>= 1)
            mval = fmaxf(mval, __shfl_xor_sync(0xffffffffu, mval, off));
        float ssum = 0.f;
        for (int t = tid; t < NTOP; t += 32) {
            float p = __expf(logits[t] - mval);
            probs[t] = p; ssum += p;
        }
        #pragma unroll
        for (int off = 16; off; off >>= 1)
            ssum += __shfl_xor_sync(0xffffffffu, ssum, off);
        float inv = 1.f / ssum;
        for (int t = tid; t < NTOP; t += 32) probs[t] *= inv;
    }
    __syncthreads();

    float uacc[4] = {0.f, 0.f, 0.f, 0.f};
    for (int t = 0; t < NTOP; t++) {
        float p = probs[t];
        const float* trow = tt + (size_t)t * WDIM;
        #pragma unroll
        for (int c = 0; c < 4; c++) uacc[c] += p * trow[tid + c * 256];
    }
    float* urow = ue + (size_t)(b * NGRP + g) * WDIM;
    #pragma unroll
    for (int c = 0; c < 4; c++) urow[tid + c * 256] = uacc[c];
}

// ---------------------------------------------------------------------------
// Final: out = inputs + mult(s) * ue[b, group(s)]
// ---------------------------------------------------------------------------
__global__ void __launch_bounds__(256) final_add(
    const float* __restrict__ inp, const int* __restrict__ in_ids,
    const int* __restrict__ res_ids, const float* __restrict__ ue,
    float* __restrict__ out)
{
    const int row = blockIdx.x, tid = threadIdx.x;
    const int b = row >> 9, s = row & 511;
    int g = 0; float mult = 0.f;
    if (s < S_IN) {
        int id = in_ids[b * S_IN + s];
        if (id > 0)      { g = id - 1;  mult = 1.f; }
        else if (id < 0) { g = -id - 1; mult = 2.f; }
    } else {
        int id = res_ids[b * 129 + (s - S_IN + 1)];
        g = 6;
        if (id > 0)      mult = 1.f;
        else if (id < 0) mult = 2.f;
    }
    const size_t base = (size_t)row * WDIM;
    const float* urow = ue + (size_t)(b * NGRP + g) * WDIM;
    #pragma unroll
    for (int c = 0; c < 4; c++) {
        int w = tid + c * 256;
        out[base + w] = inp[base + w] + mult * urow[w];
    }
}

// ---------------------------------------------------------------------------
// Launch
// ---------------------------------------------------------------------------
extern "C" void kernel_launch(void* const* d_in, const int* in_sizes, int n_in,
                              void* d_out, int out_size)
{
    const float* inp     = (const float*)d_in[0];
    const int*   in_ids  = (const int*)  d_in[1];
    const int*   res_ids = (const int*)  d_in[2];
    const float* Wqkv    = (const float*)d_in[3];
    const float* bqkv    = (const float*)d_in[4];
    const float* Wo      = (const float*)d_in[5];
    const float* bo      = (const float*)d_in[6];
    const float* ln1g    = (const float*)d_in[7];
    const float* ln1b    = (const float*)d_in[8];
    const float* W1      = (const float*)d_in[9];
    const float* b1      = (const float*)d_in[10];
    const float* W2      = (const float*)d_in[11];
    const float* b2      = (const float*)d_in[12];
    const float* ln2g    = (const float*)d_in[13];
    const float* ln2b    = (const float*)d_in[14];
    const float* tw      = (const float*)d_in[15];
    const float* tb      = (const float*)d_in[16];
    const float* tt      = (const float*)d_in[17];
    float* out = (float*)d_out;

    float *qkv, *ctx, *tmp, *y, *ff, *hidden, *ue;
    cudaGetSymbolAddress((void**)&qkv,    g_qkv);
    cudaGetSymbolAddress((void**)&ctx,    g_ctx);
    cudaGetSymbolAddress((void**)&tmp,    g_tmp);
    cudaGetSymbolAddress((void**)&y,      g_y);
    cudaGetSymbolAddress((void**)&ff,     g_ff);
    cudaGetSymbolAddress((void**)&hidden, g_hidden);
    cudaGetSymbolAddress((void**)&ue,     g_ue);

    cudaFuncSetAttribute(attn_flash,
                         cudaFuncAttributeMaxDynamicSharedMemorySize, ATT_SMEM);

    // 1) QKV projection
    gemm_nt<0><<<dim3(3 * WDIM / 64, MTOT / 64), 256>>>(
        inp, Wqkv, bqkv, qkv, MTOT, 3 * WDIM, WDIM);
    // 2) Attention
    attn_flash<<<dim3(SEQ / 64, HEADS, BATCH), 256, ATT_SMEM>>>(qkv, ctx);
    // 3) Output projection
    gemm_nt<0><<<dim3(WDIM / 64, MTOT / 64), 256>>>(
        ctx, Wo, bo, tmp, MTOT, WDIM, WDIM);
    // 4) LN1(x + attn)
    ln_residual<<<MTOT, 256>>>(inp, tmp, ln1g, ln1b, y);
    // 5) FF1 + GELU
    gemm_nt<1><<<dim3(DFFDIM / 64, MTOT / 64), 256>>>(
        y, W1, b1, ff, MTOT, DFFDIM, WDIM);
    // 6) FF2
    gemm_nt<0><<<dim3(WDIM / 64, MTOT / 64), 256>>>(
        ff, W2, b2, tmp, MTOT, WDIM, DFFDIM);
    // 7) LN2(y + ff)
    ln_residual<<<MTOT, 256>>>(y, tmp, ln2g, ln2b, hidden);
    // 8) Topic embeddings per (group, batch)
    topic_kernel<<<dim3(NGRP, BATCH), 256>>>(hidden, in_ids, res_ids, tw, tb, tt, ue);
    // 9) Final scatter-add
    final_add<<<MTOT, 256>>>(inp, in_ids, res_ids, ue, out);
}

// round 10
// speedup vs baseline: 3.1493x; 3.1493x over previous
#include <cuda_runtime.h>
#include <cuda_bf16.h>
#include <math.h>
#include <cstdint>

// ---------------------------------------------------------------------------
// Problem constants
// ---------------------------------------------------------------------------
#define BATCH   16
#define SEQ     512
#define S_IN    384
#define WDIM    1024
#define HEADS   16
#define DH      64
#define DFFDIM  4096
#define NTOP    50
#define NGRP    7
#define MTOT    (BATCH*SEQ)          // 8192 rows

// ---------------------------------------------------------------------------
// Scratch (static device globals)
// ---------------------------------------------------------------------------
__device__ __align__(256) float g_qkv[(size_t)MTOT * 3 * WDIM];
__device__ __align__(256) float g_tmp[(size_t)MTOT * WDIM];
__device__ __align__(256) float g_y[(size_t)MTOT * WDIM];
__device__ __align__(256) float g_hidden[(size_t)MTOT * WDIM];
__device__ __align__(256) float g_ue[(size_t)BATCH * NGRP * WDIM];

__device__ __align__(256) __nv_bfloat16 g_inp_h[(size_t)MTOT * WDIM];
__device__ __align__(256) __nv_bfloat16 g_inp_l[(size_t)MTOT * WDIM];
__device__ __align__(256) __nv_bfloat16 g_ctx_h[(size_t)MTOT * WDIM];
__device__ __align__(256) __nv_bfloat16 g_ctx_l[(size_t)MTOT * WDIM];
__device__ __align__(256) __nv_bfloat16 g_yh[(size_t)MTOT * WDIM];
__device__ __align__(256) __nv_bfloat16 g_yl[(size_t)MTOT * WDIM];
__device__ __align__(256) __nv_bfloat16 g_ffh[(size_t)MTOT * DFFDIM];
__device__ __align__(256) __nv_bfloat16 g_ffl[(size_t)MTOT * DFFDIM];
__device__ __align__(256) __nv_bfloat16 g_wqkv_h[(size_t)3 * WDIM * WDIM];
__device__ __align__(256) __nv_bfloat16 g_wqkv_l[(size_t)3 * WDIM * WDIM];
__device__ __align__(256) __nv_bfloat16 g_wo_h[(size_t)WDIM * WDIM];
__device__ __align__(256) __nv_bfloat16 g_wo_l[(size_t)WDIM * WDIM];
__device__ __align__(256) __nv_bfloat16 g_w1_h[(size_t)DFFDIM * WDIM];
__device__ __align__(256) __nv_bfloat16 g_w1_l[(size_t)DFFDIM * WDIM];
__device__ __align__(256) __nv_bfloat16 g_w2_h[(size_t)WDIM * DFFDIM];
__device__ __align__(256) __nv_bfloat16 g_w2_l[(size_t)WDIM * DFFDIM];

__device__ __forceinline__ float gelu_exact(float x) {
    return 0.5f * x * (1.0f + erff(x * 0.70710678118654752f));
}

// ---------------------------------------------------------------------------
// PTX helpers
// ---------------------------------------------------------------------------
__device__ __forceinline__ uint32_t smem_u32(const void* p) {
    uint32_t a;
    asm("{ .reg .u64 t; cvta.to.shared.u64 t, %1; cvt.u32.u64 %0, t; }"
        : "=r"(a) : "l"(p));
    return a;
}
#define SWZ128(off) ((off) ^ (((off) >> 3) & 0x70))

#define CP16(dst, src) \
    asm volatile("cp.async.cg.shared.global [%0], [%1], 16;" \
        :: "r"(dst), "l"(__cvta_generic_to_global(src)) : "memory")
#define CP_COMMIT() asm volatile("cp.async.commit_group;" ::: "memory")
#define CP_WAIT1() asm volatile("cp.async.wait_group 1;" ::: "memory")
#define CP_WAIT0() asm volatile("cp.async.wait_group 0;" ::: "memory")

__device__ __forceinline__ void ldsm4(uint32_t r[4], uint32_t addr) {
    asm volatile("ldmatrix.sync.aligned.m8n8.x4.shared.b16 {%0,%1,%2,%3}, [%4];"
        : "=r"(r[0]), "=r"(r[1]), "=r"(r[2]), "=r"(r[3]) : "r"(addr));
}

__device__ __forceinline__ void mma16816(float d[4], const uint32_t a[4], const uint32_t b[2]) {
    asm volatile(
        "mma.sync.aligned.m16n8k16.row.col.f32.bf16.bf16.f32 "
        "{%0,%1,%2,%3}, {%4,%5,%6,%7}, {%8,%9}, {%0,%1,%2,%3};"
        : "+f"(d[0]), "+f"(d[1]), "+f"(d[2]), "+f"(d[3])
        : "r"(a[0]), "r"(a[1]), "r"(a[2]), "r"(a[3]), "r"(b[0]), "r"(b[1]));
}

// ---------------------------------------------------------------------------
// fp32 -> (bf16 hi, bf16 lo) split
// ---------------------------------------------------------------------------
__device__ __forceinline__ void split2(float a, float b, __nv_bfloat162& h2, __nv_bfloat162& l2) {
    __nv_bfloat16 ah = __float2bfloat16(a), bh = __float2bfloat16(b);
    h2.x = ah; h2.y = bh;
    l2.x = __float2bfloat16(a - __bfloat162float(ah));
    l2.y = __float2bfloat16(b - __bfloat162float(bh));
}

__global__ void __launch_bounds__(256) split_f32(
    const float* __restrict__ src, __nv_bfloat16* __restrict__ hi,
    __nv_bfloat16* __restrict__ lo, int n4)
{
    int i = blockIdx.x * 256 + threadIdx.x;
    if (i >= n4) return;
    float4 v = ((const float4*)src)[i];
    __nv_bfloat162 h0, l0, h1, l1;
    split2(v.x, v.y, h0, l0);
    split2(v.z, v.w, h1, l1);
    ((__nv_bfloat162*)hi)[2 * i]     = h0;
    ((__nv_bfloat162*)hi)[2 * i + 1] = h1;
    ((__nv_bfloat162*)lo)[2 * i]     = l0;
    ((__nv_bfloat162*)lo)[2 * i + 1] = l1;
}

// ---------------------------------------------------------------------------
// mma.sync split-bf16 GEMM: C[M,N] = (Ahi+Alo)[M,K] @ (Bhi+Blo)[N,K]^T + bias
// 3 K-segments: hi*hi + hi*lo + lo*hi. CTA 128x128, 8 warps (2M x 4N),
// warp tile 64x32, 3-stage cp.async ring, SW128-swizzled SMEM + ldmatrix.
// ---------------------------------------------------------------------------
#define GEMM_SMEM (1024 + 3 * 32768)

template<int DO_GELU, int WF32, int WSPLIT>
__global__ void __launch_bounds__(256, 2) gemm_mma(
    const __nv_bfloat16* __restrict__ Ahi, const __nv_bfloat16* __restrict__ Alo,
    const __nv_bfloat16* __restrict__ Bhi, const __nv_bfloat16* __restrict__ Blo,
    const float* __restrict__ bias,
    float* __restrict__ Cf, __nv_bfloat16* __restrict__ Chi, __nv_bfloat16* __restrict__ Clo,
    int N, int K)
{
    extern __shared__ char smraw[];
    const uint32_t sb = (smem_u32(smraw) + 1023u) & ~1023u;
    const int tid = threadIdx.x;
    const int wid = tid >> 5, lane = tid & 31;
    const int wm = wid >> 2, wn = wid & 3;      // 2 x 4 warp grid
    const int m0 = blockIdx.y << 7, n0 = blockIdx.x << 7;
    const int KC = K >> 6;
    const int NC = 3 * KC;

    auto load_chunk = [&](int c, int s) {
        const int seg = c / KC;
        const int k0 = (c - seg * KC) << 6;
        const __nv_bfloat16* As = (seg == 2) ? Alo : Ahi;
        const __nv_bfloat16* Bs = (seg == 1) ? Blo : Bhi;
        const uint32_t stA = sb + s * 32768;
        const uint32_t stB = stA + 16384;
        #pragma unroll
        for (int j = 0; j < 4; j++) {
            int i = tid + (j << 8);                 // 0..1023
            int r = i >> 3, cc = i & 7;
            uint32_t off = SWZ128((uint32_t)(r * 128 + cc * 16));
            CP16(stA + off, As + (size_t)(m0 + r) * K + k0 + (cc << 3));
        }
        #pragma unroll
        for (int j = 0; j < 4; j++) {
            int i = tid + (j << 8);
            int r = i >> 3, cc = i & 7;
            uint32_t off = SWZ128((uint32_t)(r * 128 + cc * 16));
            CP16(stB + off, Bs + (size_t)(n0 + r) * K + k0 + (cc << 3));
        }
        CP_COMMIT();
    };

    load_chunk(0, 0);
    load_chunk(1, 1);

    float acc[4][4][4];
    #pragma unroll
    for (int mi = 0; mi < 4; mi++)
        #pragma unroll
        for (int nj = 0; nj < 4; nj++)
            #pragma unroll
            for (int q = 0; q < 4; q++) acc[mi][nj][q] = 0.f;

    // per-lane ldmatrix source coordinates
    const int a_row = wm * 64 + (lane & 15);
    const int a_kc8 = (lane >> 4) << 3;             // 0 or 8
    const int b_row = wn * 32 + (lane & 7) + ((lane & 16) ? 8 : 0);
    const int b_kc8 = (lane & 8);                   // 0 or 8

    for (int c = 0; c < NC; c++) {
        if (c < NC - 1) CP_WAIT1(); else CP_WAIT0();
        __syncthreads();
        if (c + 2 < NC) load_chunk(c + 2, (c + 2) % 3);

        const uint32_t stA = sb + (c % 3) * 32768;
        const uint32_t stB = stA + 16384;
        #pragma unroll
        for (int kk = 0; kk < 4; kk++) {
            const int k0 = kk << 4;
            uint32_t a[4][4];
            #pragma unroll
            for (int mi = 0; mi < 4; mi++) {
                uint32_t off = (uint32_t)((a_row + mi * 16) * 128 + (k0 + a_kc8) * 2);
                ldsm4(a[mi], stA + SWZ128(off));
            }
            uint32_t b[4][2];
            #pragma unroll
            for (int pr = 0; pr < 2; pr++) {
                uint32_t r4[4];
                uint32_t off = (uint32_t)((b_row + pr * 16) * 128 + (k0 + b_kc8) * 2);
                ldsm4(r4, stB + SWZ128(off));
                b[pr * 2][0] = r4[0]; b[pr * 2][1] = r4[1];
                b[pr * 2 + 1][0] = r4[2]; b[pr * 2 + 1][1] = r4[3];
            }
            #pragma unroll
            for (int mi = 0; mi < 4; mi++)
                #pragma unroll
                for (int nj = 0; nj < 4; nj++)
                    mma16816(acc[mi][nj], a[mi], b[nj]);
        }
        __syncthreads();
    }

    // epilogue: bias (+GELU) (+split) straight from registers
    const int r_base = m0 + wm * 64 + (lane >> 2);
    const int c_base = n0 + wn * 32 + 2 * (lane & 3);
    #pragma unroll
    for (int nj = 0; nj < 4; nj++) {
        const int col = c_base + nj * 8;
        const float b0 = bias[col], b1 = bias[col + 1];
        #pragma unroll
        for (int mi = 0; mi < 4; mi++) {
            #pragma unroll
            for (int h = 0; h < 2; h++) {
                const int row = r_base + mi * 16 + h * 8;
                float x0 = acc[mi][nj][2 * h]     + b0;
                float x1 = acc[mi][nj][2 * h + 1] + b1;
                if (DO_GELU) { x0 = gelu_exact(x0); x1 = gelu_exact(x1); }
                if (WF32) {
                    *(float2*)(Cf + (size_t)row * N + col) = make_float2(x0, x1);
                }
                if (WSPLIT) {
                    __nv_bfloat162 h2, l2;
                    split2(x0, x1, h2, l2);
                    *(__nv_bfloat162*)(Chi + (size_t)row * N + col) = h2;
                    *(__nv_bfloat162*)(Clo + (size_t)row * N + col) = l2;
                }
            }
        }
    }
}

// ---------------------------------------------------------------------------
// Flash attention (fp32 SIMT), writes split-bf16 ctx for the O-projection.
// ---------------------------------------------------------------------------
#define ATT_STRIDE 68
#define ATT_SMEM (4 * 64 * ATT_STRIDE * 4)

__global__ void __launch_bounds__(256) attn_flash(
    const float* __restrict__ qkv,
    __nv_bfloat16* __restrict__ ctx_h, __nv_bfloat16* __restrict__ ctx_l)
{
    extern __shared__ float sm[];
    float* Qs = sm;
    float* Ks = sm + 64 * ATT_STRIDE;
    float* Vs = sm + 2 * 64 * ATT_STRIDE;
    float* Ps = sm + 3 * 64 * ATT_STRIDE;

    const int tid = threadIdx.x;
    const int tx = tid & 15, ty = tid >> 4;
    const int qt = blockIdx.x, h = blockIdx.y, b = blockIdx.z;
    const size_t rowbase = (size_t)b * SEQ * 3 * WDIM;
    const int hoff = h * DH;

    for (int idx = tid; idx < 64 * 64; idx += 256) {
        int qi = idx >> 6, d = idx & 63;
        Qs[d * ATT_STRIDE + qi] =
            qkv[rowbase + (size_t)(qt * 64 + qi) * 3 * WDIM + hoff + d] * 0.125f;
    }

    float m_i[4], l_i[4], O[4][4];
    #pragma unroll
    for (int i = 0; i < 4; i++) {
        m_i[i] = -1e30f; l_i[i] = 0.f;
        #pragma unroll
        for (int j = 0; j < 4; j++) O[i][j] = 0.f;
    }

    for (int kt = 0; kt < SEQ / 64; kt++) {
        __syncthreads();
        for (int idx = tid; idx < 64 * 64; idx += 256) {
            int r = idx >> 6, d = idx & 63;
            size_t base = rowbase + (size_t)(kt * 64 + r) * 3 * WDIM + hoff;
            Ks[d * ATT_STRIDE + r] = qkv[base + WDIM + d];
            Vs[r * ATT_STRIDE + d] = qkv[base + 2 * WDIM + d];
        }
        __syncthreads();

        float s[4][4] = {};
        #pragma unroll 8
        for (int d = 0; d < 64; d++) {
            float4 a  = *(const float4*)&Qs[d * ATT_STRIDE + (ty << 2)];
            float4 kq = *(const float4*)&Ks[d * ATT_STRIDE + (tx << 2)];
            s[0][0] += a.x * kq.x; s[0][1] += a.x * kq.y; s[0][2] += a.x * kq.z; s[0][3] += a.x * kq.w;
            s[1][0] += a.y * kq.x; s[1][1] += a.y * kq.y; s[1][2] += a.y * kq.z; s[1][3] += a.y * kq.w;
            s[2][0] += a.z * kq.x; s[2][1] += a.z * kq.y; s[2][2] += a.z * kq.z; s[2][3] += a.z * kq.w;
            s[3][0] += a.w * kq.x; s[3][1] += a.w * kq.y; s[3][2] += a.w * kq.z; s[3][3] += a.w * kq.w;
        }

        #pragma unroll
        for (int i = 0; i < 4; i++) {
            float tmax = fmaxf(fmaxf(s[i][0], s[i][1]), fmaxf(s[i][2], s[i][3]));
            #pragma unroll
            for (int off = 8; off; off >>= 1)
                tmax = fmaxf(tmax, __shfl_xor_sync(0xffffffffu, tmax, off));
            float nm = fmaxf(m_i[i], tmax);
            float alpha = __expf(m_i[i] - nm);
            m_i[i] = nm;
            float rs = 0.f;
            #pragma unroll
            for (int j = 0; j < 4; j++) {
                float p = __expf(s[i][j] - nm);
                s[i][j] = p; rs += p;
            }
            #pragma unroll
            for (int off = 8; off; off >>= 1)
                rs += __shfl_xor_sync(0xffffffffu, rs, off);
            l_i[i] = l_i[i] * alpha + rs;
            #pragma unroll
            for (int j = 0; j < 4; j++) O[i][j] *= alpha;
        }

        #pragma unroll
        for (int i = 0; i < 4; i++)
            #pragma unroll
            for (int j = 0; j < 4; j++)
                Ps[((tx << 2) + j) * ATT_STRIDE + (ty << 2) + i] = s[i][j];
        __syncthreads();

        #pragma unroll 8
        for (int kr = 0; kr < 64; kr++) {
            float4 p = *(const float4*)&Ps[kr * ATT_STRIDE + (ty << 2)];
            float4 v = *(const float4*)&Vs[kr * ATT_STRIDE + (tx << 2)];
            O[0][0] += p.x * v.x; O[0][1] += p.x * v.y; O[0][2] += p.x * v.z; O[0][3] += p.x * v.w;
            O[1][0] += p.y * v.x; O[1][1] += p.y * v.y; O[1][2] += p.y * v.z; O[1][3] += p.y * v.w;
            O[2][0] += p.z * v.x; O[2][1] += p.z * v.y; O[2][2] += p.z * v.z; O[2][3] += p.z * v.w;
            O[3][0] += p.w * v.x; O[3][1] += p.w * v.y; O[3][2] += p.w * v.z; O[3][3] += p.w * v.w;
        }
        __syncthreads();
    }

    #pragma unroll
    for (int i = 0; i < 4; i++) {
        float inv = 1.f / l_i[i];
        size_t idx = (size_t)(b * SEQ + qt * 64 + (ty << 2) + i) * WDIM + hoff + (tx << 2);
        __nv_bfloat162 h0, l0, h1, l1;
        split2(O[i][0] * inv, O[i][1] * inv, h0, l0);
        split2(O[i][2] * inv, O[i][3] * inv, h1, l1);
        __nv_bfloat162* ph = (__nv_bfloat162*)(ctx_h + idx);
        __nv_bfloat162* pl = (__nv_bfloat162*)(ctx_l + idx);
        ph[0] = h0; ph[1] = h1;
        pl[0] = l0; pl[1] = l1;
    }
}

// ---------------------------------------------------------------------------
// Residual add + LayerNorm; optionally also writes split-bf16 output.
// ---------------------------------------------------------------------------
template<int SPLIT>
__global__ void __launch_bounds__(256) ln_residual(
    const float* __restrict__ x, const float* __restrict__ r,
    const float* __restrict__ gamma, const float* __restrict__ beta,
    float* __restrict__ out, __nv_bfloat16* __restrict__ oh, __nv_bfloat16* __restrict__ ol)
{
    __shared__ float red[2][8];
    __shared__ float stats[2];
    const int row = blockIdx.x, tid = threadIdx.x;
    const size_t base = (size_t)row * WDIM;
    float v[4];
    float s = 0.f, sq = 0.f;
    #pragma unroll
    for (int c = 0; c < 4; c++) {
        int w = tid + c * 256;
        float a = x[base + w] + r[base + w];
        v[c] = a; s += a; sq += a * a;
    }
    #pragma unroll
    for (int off = 16; off; off >>= 1) {
        s  += __shfl_xor_sync(0xffffffffu, s, off);
        sq += __shfl_xor_sync(0xffffffffu, sq, off);
    }
    int lane = tid & 31, wid = tid >> 5;
    if (lane == 0) { red[0][wid] = s; red[1][wid] = sq; }
    __syncthreads();
    if (tid == 0) {
        float ts = 0.f, tq = 0.f;
        #pragma unroll
        for (int w = 0; w < 8; w++) { ts += red[0][w]; tq += red[1][w]; }
        float mean = ts * (1.f / WDIM);
        float var  = tq * (1.f / WDIM) - mean * mean;
        stats[0] = mean;
        stats[1] = rsqrtf(var + 1e-5f);
    }
    __syncthreads();
    float mean = stats[0], rstd = stats[1];
    #pragma unroll
    for (int c = 0; c < 4; c++) {
        int w = tid + c * 256;
        float o = (v[c] - mean) * rstd * gamma[w] + beta[w];
        out[base + w] = o;
        if (SPLIT) {
            __nv_bfloat16 hh = __float2bfloat16(o);
            oh[base + w] = hh;
            ol[base + w] = __float2bfloat16(o - __bfloat162float(hh));
        }
    }
}

// ---------------------------------------------------------------------------
// Topic kernel
// ---------------------------------------------------------------------------
__global__ void __launch_bounds__(256) topic_kernel(
    const float* __restrict__ hidden, const int* __restrict__ in_ids,
    const int* __restrict__ res_ids, const float* __restrict__ tw,
    const float* __restrict__ tb, const float* __restrict__ tt,
    float* __restrict__ ue)
{
    __shared__ float mp[WDIM];
    __shared__ float logits[64];
    __shared__ float probs[64];
    __shared__ int sid[SEQ];
    const int tid = threadIdx.x;
    const int g = blockIdx.x, b = blockIdx.y;

    for (int s = tid; s < SEQ; s += 256) {
        int id;
        if (g < 6) id = (s < S_IN) ? in_ids[b * S_IN + s] : 0;
        else       id = (s >= S_IN) ? res_ids[b * 129 + (s - S_IN + 1)] : 0;
        sid[s] = id;
    }
    __syncthreads();

    const int gid = (g < 6) ? (g + 1) : 1;
    float acc[4] = {0.f, 0.f, 0.f, 0.f};
    for (int s = 0; s < SEQ; s++) {
        if (sid[s] == gid) {
            const float* hr = hidden + (size_t)(b * SEQ + s) * WDIM;
            #pragma unroll
            for (int c = 0; c < 4; c++)
                acc[c] = fmaxf(acc[c], hr[tid + c * 256]);
        }
    }
    #pragma unroll
    for (int c = 0; c < 4; c++) mp[tid + c * 256] = acc[c];
    __syncthreads();

    int lane = tid & 31, wid = tid >> 5;
    for (int t = wid; t < NTOP; t += 8) {
        const float* wrow = tw + (size_t)t * WDIM;
        float d = 0.f;
        for (int w = lane; w < WDIM; w += 32) d += mp[w] * wrow[w];
        #pragma unroll
        for (int off = 16; off; off >>= 1)
            d += __shfl_xor_sync(0xffffffffu, d, off);
        if (lane == 0) logits[t] = d + tb[t];
    }
    __syncthreads();

    if (tid < 32) {
        float mval = -1e30f;
        for (int t = tid; t < NTOP; t += 32) mval = fmaxf(mval, logits[t]);
        #pragma unroll
        for (int off = 16; off; off >>= 1)
            mval = fmaxf(mval, __shfl_xor_sync(0xffffffffu, mval, off));
        float ssum = 0.f;
        for (int t = tid; t < NTOP; t += 32) {
            float p = __expf(logits[t] - mval);
            probs[t] = p; ssum += p;
        }
        #pragma unroll
        for (int off = 16; off; off >>= 1)
            ssum += __shfl_xor_sync(0xffffffffu, ssum, off);
        float inv = 1.f / ssum;
        for (int t = tid; t < NTOP; t += 32) probs[t] *= inv;
    }
    __syncthreads();

    float uacc[4] = {0.f, 0.f, 0.f, 0.f};
    for (int t = 0; t < NTOP; t++) {
        float p = probs[t];
        const float* trow = tt + (size_t)t * WDIM;
        #pragma unroll
        for (int c = 0; c < 4; c++) uacc[c] += p * trow[tid + c * 256];
    }
    float* urow = ue + (size_t)(b * NGRP + g) * WDIM;
    #pragma unroll
    for (int c = 0; c < 4; c++) urow[tid + c * 256] = uacc[c];
}

// ---------------------------------------------------------------------------
// Final scatter-add
// ---------------------------------------------------------------------------
__global__ void __launch_bounds__(256) final_add(
    const float* __restrict__ inp, const int* __restrict__ in_ids,
    const int* __restrict__ res_ids, const float* __restrict__ ue,
    float* __restrict__ out)
{
    const int row = blockIdx.x, tid = threadIdx.x;
    const int b = row >> 9, s = row & 511;
    int g = 0; float mult = 0.f;
    if (s < S_IN) {
        int id = in_ids[b * S_IN + s];
        if (id > 0)      { g = id - 1;  mult = 1.f; }
        else if (id < 0) { g = -id - 1; mult = 2.f; }
    } else {
        int id = res_ids[b * 129 + (s - S_IN + 1)];
        g = 6;
        if (id > 0)      mult = 1.f;
        else if (id < 0) mult = 2.f;
    }
    const size_t base = (size_t)row * WDIM;
    const float* urow = ue + (size_t)(b * NGRP + g) * WDIM;
    #pragma unroll
    for (int c = 0; c < 4; c++) {
        int w = tid + c * 256;
        out[base + w] = inp[base + w] + mult * urow[w];
    }
}

// ---------------------------------------------------------------------------
// Launch
// ---------------------------------------------------------------------------
extern "C" void kernel_launch(void* const* d_in, const int* in_sizes, int n_in,
                              void* d_out, int out_size)
{
    const float* inp     = (const float*)d_in[0];
    const int*   in_ids  = (const int*)  d_in[1];
    const int*   res_ids = (const int*)  d_in[2];
    const float* Wqkv    = (const float*)d_in[3];
    const float* bqkv    = (const float*)d_in[4];
    const float* Wo      = (const float*)d_in[5];
    const float* bo      = (const float*)d_in[6];
    const float* ln1g    = (const float*)d_in[7];
    const float* ln1b    = (const float*)d_in[8];
    const float* W1      = (const float*)d_in[9];
    const float* b1      = (const float*)d_in[10];
    const float* W2      = (const float*)d_in[11];
    const float* b2      = (const float*)d_in[12];
    const float* ln2g    = (const float*)d_in[13];
    const float* ln2b    = (const float*)d_in[14];
    const float* tw      = (const float*)d_in[15];
    const float* tb      = (const float*)d_in[16];
    const float* tt      = (const float*)d_in[17];
    float* out = (float*)d_out;

    float *qkv, *tmp, *y, *hidden, *ue;
    cudaGetSymbolAddress((void**)&qkv,    g_qkv);
    cudaGetSymbolAddress((void**)&tmp,    g_tmp);
    cudaGetSymbolAddress((void**)&y,      g_y);
    cudaGetSymbolAddress((void**)&hidden, g_hidden);
    cudaGetSymbolAddress((void**)&ue,     g_ue);

    __nv_bfloat16 *inp_h, *inp_l, *ctx_h, *ctx_l, *yh, *yl, *ffh, *ffl;
    __nv_bfloat16 *wqkv_h, *wqkv_l, *wo_h, *wo_l, *w1_h, *w1_l, *w2_h, *w2_l;
    cudaGetSymbolAddress((void**)&inp_h,  g_inp_h);
    cudaGetSymbolAddress((void**)&inp_l,  g_inp_l);
    cudaGetSymbolAddress((void**)&ctx_h,  g_ctx_h);
    cudaGetSymbolAddress((void**)&ctx_l,  g_ctx_l);
    cudaGetSymbolAddress((void**)&yh,     g_yh);
    cudaGetSymbolAddress((void**)&yl,     g_yl);
    cudaGetSymbolAddress((void**)&ffh,    g_ffh);
    cudaGetSymbolAddress((void**)&ffl,    g_ffl);
    cudaGetSymbolAddress((void**)&wqkv_h, g_wqkv_h);
    cudaGetSymbolAddress((void**)&wqkv_l, g_wqkv_l);
    cudaGetSymbolAddress((void**)&wo_h,   g_wo_h);
    cudaGetSymbolAddress((void**)&wo_l,   g_wo_l);
    cudaGetSymbolAddress((void**)&w1_h,   g_w1_h);
    cudaGetSymbolAddress((void**)&w1_l,   g_w1_l);
    cudaGetSymbolAddress((void**)&w2_h,   g_w2_h);
    cudaGetSymbolAddress((void**)&w2_l,   g_w2_l);

    cudaFuncSetAttribute(attn_flash,
                         cudaFuncAttributeMaxDynamicSharedMemorySize, ATT_SMEM);
    cudaFuncSetAttribute(gemm_mma<0,1,0>,
                         cudaFuncAttributeMaxDynamicSharedMemorySize, GEMM_SMEM);
    cudaFuncSetAttribute(gemm_mma<1,0,1>,
                         cudaFuncAttributeMaxDynamicSharedMemorySize, GEMM_SMEM);

    // 0) fp32 -> split-bf16 conversions (inputs + weights)
    auto launch_split = [&](const float* s, __nv_bfloat16* h, __nv_bfloat16* l, size_t n) {
        int n4 = (int)(n / 4);
        split_f32<<<(n4 + 255) / 256, 256>>>(s, h, l, n4);
    };
    launch_split(inp,  inp_h,  inp_l,  (size_t)MTOT * WDIM);
    launch_split(Wqkv, wqkv_h, wqkv_l, (size_t)3 * WDIM * WDIM);
    launch_split(Wo,   wo_h,   wo_l,   (size_t)WDIM * WDIM);
    launch_split(W1,   w1_h,   w1_l,   (size_t)DFFDIM * WDIM);
    launch_split(W2,   w2_h,   w2_l,   (size_t)WDIM * DFFDIM);

    // 1) QKV projection: qkv = inp @ Wqkv^T + bqkv
    gemm_mma<0,1,0><<<dim3(3 * WDIM / 128, MTOT / 128), 256, GEMM_SMEM>>>(
        inp_h, inp_l, wqkv_h, wqkv_l, bqkv, qkv, nullptr, nullptr, 3 * WDIM, WDIM);
    // 2) Attention (fp32 SIMT) -> split ctx
    attn_flash<<<dim3(SEQ / 64, HEADS, BATCH), 256, ATT_SMEM>>>(qkv, ctx_h, ctx_l);
    // 3) O projection: tmp = ctx @ Wo^T + bo
    gemm_mma<0,1,0><<<dim3(WDIM / 128, MTOT / 128), 256, GEMM_SMEM>>>(
        ctx_h, ctx_l, wo_h, wo_l, bo, tmp, nullptr, nullptr, WDIM, WDIM);
    // 4) LN1(inp + tmp) -> y (fp32 + split)
    ln_residual<1><<<MTOT, 256>>>(inp, tmp, ln1g, ln1b, y, yh, yl);
    // 5) FF1 + GELU -> split ff only
    gemm_mma<1,0,1><<<dim3(DFFDIM / 128, MTOT / 128), 256, GEMM_SMEM>>>(
        yh, yl, w1_h, w1_l, b1, nullptr, ffh, ffl, DFFDIM, WDIM);
    // 6) FF2: tmp = ff @ W2^T + b2
    gemm_mma<0,1,0><<<dim3(WDIM / 128, MTOT / 128), 256, GEMM_SMEM>>>(
        ffh, ffl, w2_h, w2_l, b2, tmp, nullptr, nullptr, WDIM, DFFDIM);
    // 7) LN2(y + tmp) -> hidden
    ln_residual<0><<<MTOT, 256>>>(y, tmp, ln2g, ln2b, hidden, nullptr, nullptr);
    // 8) Topic embeddings
    topic_kernel<<<dim3(NGRP, BATCH), 256>>>(hidden, in_ids, res_ids, tw, tb, tt, ue);
    // 9) Final scatter-add
    final_add<<<MTOT, 256>>>(inp, in_ids, res_ids, ue, out);
}

// round 12
// speedup vs baseline: 3.4766x; 1.1039x over previous
#include <cuda_runtime.h>
#include <cuda_bf16.h>
#include <math.h>
#include <cstdint>

// ---------------------------------------------------------------------------
// Problem constants
// ---------------------------------------------------------------------------
#define BATCH   16
#define SEQ     512
#define S_IN    384
#define WDIM    1024
#define HEADS   16
#define DH      64
#define DFFDIM  4096
#define NTOP    50
#define NGRP    7
#define MTOT    (BATCH*SEQ)          // 8192 rows

// ---------------------------------------------------------------------------
// Scratch (static device globals)
// ---------------------------------------------------------------------------
__device__ __align__(256) float g_qkv[(size_t)MTOT * 3 * WDIM];
__device__ __align__(256) float g_tmp[(size_t)MTOT * WDIM];
__device__ __align__(256) float g_y[(size_t)MTOT * WDIM];
__device__ __align__(256) float g_hidden[(size_t)MTOT * WDIM];
__device__ __align__(256) float g_ue[(size_t)BATCH * NGRP * WDIM];

__device__ __align__(256) __nv_bfloat16 g_inp_h[(size_t)MTOT * WDIM];
__device__ __align__(256) __nv_bfloat16 g_inp_l[(size_t)MTOT * WDIM];
__device__ __align__(256) __nv_bfloat16 g_ctx_h[(size_t)MTOT * WDIM];
__device__ __align__(256) __nv_bfloat16 g_ctx_l[(size_t)MTOT * WDIM];
__device__ __align__(256) __nv_bfloat16 g_yh[(size_t)MTOT * WDIM];
__device__ __align__(256) __nv_bfloat16 g_yl[(size_t)MTOT * WDIM];
__device__ __align__(256) __nv_bfloat16 g_ffh[(size_t)MTOT * DFFDIM];
__device__ __align__(256) __nv_bfloat16 g_ffl[(size_t)MTOT * DFFDIM];
__device__ __align__(256) __nv_bfloat16 g_wqkv_h[(size_t)3 * WDIM * WDIM];
__device__ __align__(256) __nv_bfloat16 g_wqkv_l[(size_t)3 * WDIM * WDIM];
__device__ __align__(256) __nv_bfloat16 g_wo_h[(size_t)WDIM * WDIM];
__device__ __align__(256) __nv_bfloat16 g_wo_l[(size_t)WDIM * WDIM];
__device__ __align__(256) __nv_bfloat16 g_w1_h[(size_t)DFFDIM * WDIM];
__device__ __align__(256) __nv_bfloat16 g_w1_l[(size_t)DFFDIM * WDIM];
__device__ __align__(256) __nv_bfloat16 g_w2_h[(size_t)WDIM * DFFDIM];
__device__ __align__(256) __nv_bfloat16 g_w2_l[(size_t)WDIM * DFFDIM];

__device__ __forceinline__ float gelu_exact(float x) {
    return 0.5f * x * (1.0f + erff(x * 0.70710678118654752f));
}

// ---------------------------------------------------------------------------
// PTX helpers
// ---------------------------------------------------------------------------
__device__ __forceinline__ uint32_t smem_u32(const void* p) {
    uint32_t a;
    asm("{ .reg .u64 t; cvta.to.shared.u64 t, %1; cvt.u32.u64 %0, t; }"
        : "=r"(a) : "l"(p));
    return a;
}
#define SWZ128(off) ((off) ^ (((off) >> 3) & 0x70))

#define CP16(dst, src) \
    asm volatile("cp.async.cg.shared.global [%0], [%1], 16;" \
        :: "r"(dst), "l"(__cvta_generic_to_global(src)) : "memory")
#define CP_COMMIT() asm volatile("cp.async.commit_group;" ::: "memory")
#define CP_WAIT1() asm volatile("cp.async.wait_group 1;" ::: "memory")
#define CP_WAIT0() asm volatile("cp.async.wait_group 0;" ::: "memory")

__device__ __forceinline__ void ldsm4(uint32_t r[4], uint32_t addr) {
    asm volatile("ldmatrix.sync.aligned.m8n8.x4.shared.b16 {%0,%1,%2,%3}, [%4];"
        : "=r"(r[0]), "=r"(r[1]), "=r"(r[2]), "=r"(r[3]) : "r"(addr));
}

__device__ __forceinline__ void mma16816(float d[4], const uint32_t a[4], const uint32_t b[2]) {
    asm volatile(
        "mma.sync.aligned.m16n8k16.row.col.f32.bf16.bf16.f32 "
        "{%0,%1,%2,%3}, {%4,%5,%6,%7}, {%8,%9}, {%0,%1,%2,%3};"
        : "+f"(d[0]), "+f"(d[1]), "+f"(d[2]), "+f"(d[3])
        : "r"(a[0]), "r"(a[1]), "r"(a[2]), "r"(a[3]), "r"(b[0]), "r"(b[1]));
}

// ---------------------------------------------------------------------------
// fp32 -> (bf16 hi, bf16 lo) split
// ---------------------------------------------------------------------------
__device__ __forceinline__ void split2(float a, float b, __nv_bfloat162& h2, __nv_bfloat162& l2) {
    __nv_bfloat16 ah = __float2bfloat16(a), bh = __float2bfloat16(b);
    h2.x = ah; h2.y = bh;
    l2.x = __float2bfloat16(a - __bfloat162float(ah));
    l2.y = __float2bfloat16(b - __bfloat162float(bh));
}

__device__ __forceinline__ uint32_t b2u(__nv_bfloat162 v) {
    union { __nv_bfloat162 b; uint32_t u; } c; c.b = v; return c.u;
}

__global__ void __launch_bounds__(256) split_f32(
    const float* __restrict__ src, __nv_bfloat16* __restrict__ hi,
    __nv_bfloat16* __restrict__ lo, int n4)
{
    int i = blockIdx.x * 256 + threadIdx.x;
    if (i >= n4) return;
    float4 v = ((const float4*)src)[i];
    __nv_bfloat162 h0, l0, h1, l1;
    split2(v.x, v.y, h0, l0);
    split2(v.z, v.w, h1, l1);
    ((__nv_bfloat162*)hi)[2 * i]     = h0;
    ((__nv_bfloat162*)hi)[2 * i + 1] = h1;
    ((__nv_bfloat162*)lo)[2 * i]     = l0;
    ((__nv_bfloat162*)lo)[2 * i + 1] = l1;
}

// ---------------------------------------------------------------------------
// mma.sync split-bf16 GEMM (unchanged from R10 passing version)
// ---------------------------------------------------------------------------
#define GEMM_SMEM (1024 + 3 * 32768)

template<int DO_GELU, int WF32, int WSPLIT>
__global__ void __launch_bounds__(256, 2) gemm_mma(
    const __nv_bfloat16* __restrict__ Ahi, const __nv_bfloat16* __restrict__ Alo,
    const __nv_bfloat16* __restrict__ Bhi, const __nv_bfloat16* __restrict__ Blo,
    const float* __restrict__ bias,
    float* __restrict__ Cf, __nv_bfloat16* __restrict__ Chi, __nv_bfloat16* __restrict__ Clo,
    int N, int K)
{
    extern __shared__ char smraw[];
    const uint32_t sb = (smem_u32(smraw) + 1023u) & ~1023u;
    const int tid = threadIdx.x;
    const int wid = tid >> 5, lane = tid & 31;
    const int wm = wid >> 2, wn = wid & 3;      // 2 x 4 warp grid
    const int m0 = blockIdx.y << 7, n0 = blockIdx.x << 7;
    const int KC = K >> 6;
    const int NC = 3 * KC;

    auto load_chunk = [&](int c, int s) {
        const int seg = c / KC;
        const int k0 = (c - seg * KC) << 6;
        const __nv_bfloat16* As = (seg == 2) ? Alo : Ahi;
        const __nv_bfloat16* Bs = (seg == 1) ? Blo : Bhi;
        const uint32_t stA = sb + s * 32768;
        const uint32_t stB = stA + 16384;
        #pragma unroll
        for (int j = 0; j < 4; j++) {
            int i = tid + (j << 8);                 // 0..1023
            int r = i >> 3, cc = i & 7;
            uint32_t off = SWZ128((uint32_t)(r * 128 + cc * 16));
            CP16(stA + off, As + (size_t)(m0 + r) * K + k0 + (cc << 3));
        }
        #pragma unroll
        for (int j = 0; j < 4; j++) {
            int i = tid + (j << 8);
            int r = i >> 3, cc = i & 7;
            uint32_t off = SWZ128((uint32_t)(r * 128 + cc * 16));
            CP16(stB + off, Bs + (size_t)(n0 + r) * K + k0 + (cc << 3));
        }
        CP_COMMIT();
    };

    load_chunk(0, 0);
    load_chunk(1, 1);

    float acc[4][4][4];
    #pragma unroll
    for (int mi = 0; mi < 4; mi++)
        #pragma unroll
        for (int nj = 0; nj < 4; nj++)
            #pragma unroll
            for (int q = 0; q < 4; q++) acc[mi][nj][q] = 0.f;

    const int a_row = wm * 64 + (lane & 15);
    const int a_kc8 = (lane >> 4) << 3;             // 0 or 8
    const int b_row = wn * 32 + (lane & 7) + ((lane & 16) ? 8 : 0);
    const int b_kc8 = (lane & 8);                   // 0 or 8

    for (int c = 0; c < NC; c++) {
        if (c < NC - 1) CP_WAIT1(); else CP_WAIT0();
        __syncthreads();
        if (c + 2 < NC) load_chunk(c + 2, (c + 2) % 3);

        const uint32_t stA = sb + (c % 3) * 32768;
        const uint32_t stB = stA + 16384;
        #pragma unroll
        for (int kk = 0; kk < 4; kk++) {
            const int k0 = kk << 4;
            uint32_t a[4][4];
            #pragma unroll
            for (int mi = 0; mi < 4; mi++) {
                uint32_t off = (uint32_t)((a_row + mi * 16) * 128 + (k0 + a_kc8) * 2);
                ldsm4(a[mi], stA + SWZ128(off));
            }
            uint32_t b[4][2];
            #pragma unroll
            for (int pr = 0; pr < 2; pr++) {
                uint32_t r4[4];
                uint32_t off = (uint32_t)((b_row + pr * 16) * 128 + (k0 + b_kc8) * 2);
                ldsm4(r4, stB + SWZ128(off));
                b[pr * 2][0] = r4[0]; b[pr * 2][1] = r4[1];
                b[pr * 2 + 1][0] = r4[2]; b[pr * 2 + 1][1] = r4[3];
            }
            #pragma unroll
            for (int mi = 0; mi < 4; mi++)
                #pragma unroll
                for (int nj = 0; nj < 4; nj++)
                    mma16816(acc[mi][nj], a[mi], b[nj]);
        }
        __syncthreads();
    }

    const int r_base = m0 + wm * 64 + (lane >> 2);
    const int c_base = n0 + wn * 32 + 2 * (lane & 3);
    #pragma unroll
    for (int nj = 0; nj < 4; nj++) {
        const int col = c_base + nj * 8;
        const float b0 = bias[col], b1 = bias[col + 1];
        #pragma unroll
        for (int mi = 0; mi < 4; mi++) {
            #pragma unroll
            for (int h = 0; h < 2; h++) {
                const int row = r_base + mi * 16 + h * 8;
                float x0 = acc[mi][nj][2 * h]     + b0;
                float x1 = acc[mi][nj][2 * h + 1] + b1;
                if (DO_GELU) { x0 = gelu_exact(x0); x1 = gelu_exact(x1); }
                if (WF32) {
                    *(float2*)(Cf + (size_t)row * N + col) = make_float2(x0, x1);
                }
                if (WSPLIT) {
                    __nv_bfloat162 h2, l2;
                    split2(x0, x1, h2, l2);
                    *(__nv_bfloat162*)(Chi + (size_t)row * N + col) = h2;
                    *(__nv_bfloat162*)(Clo + (size_t)row * N + col) = l2;
                }
            }
        }
    }
}

// ---------------------------------------------------------------------------
// Flash attention, tensor-core split-bf16.
// One CTA per (b, h, 64-query tile); 4 warps, each owns 16 q-rows.
// QK^T: Qh*Kh + Qh*Kl + Ql*Kh (fp32 acc). Online softmax in registers.
// P re-split in-register; PV: Ph*Vh + Pl*Vh + Ph*Vl with V transposed in smem.
// SMEM: Qh|Ql|Kh|Kl|Vth|Vtl, 8KB each (64 rows x 128B, SW128 swizzled).
// ---------------------------------------------------------------------------
#define ATT_SMEM 49152

__global__ void __launch_bounds__(128) attn_flash(
    const float* __restrict__ qkv,
    __nv_bfloat16* __restrict__ ctx_h, __nv_bfloat16* __restrict__ ctx_l)
{
    extern __shared__ char smraw[];
    const uint32_t sb = smem_u32(smraw);
    const uint32_t sQh = sb, sQl = sb + 8192;
    const uint32_t sKh = sb + 16384, sKl = sb + 24576;
    const uint32_t sVh = sb + 32768, sVl = sb + 40960;

    const int tid = threadIdx.x;
    const int wid = tid >> 5, lane = tid & 31;
    const int qt = blockIdx.x, h = blockIdx.y, b = blockIdx.z;
    const size_t rowbase = (size_t)b * SEQ * 3 * WDIM;
    const int hoff = h * DH;

    // ---- load Q tile (scaled by 1/sqrt(dh)), split into smem ----
    for (int e = tid; e < 1024; e += 128) {
        int r = e >> 4, d4 = (e & 15) << 2;
        float4 v = *(const float4*)(qkv + rowbase + (size_t)(qt * 64 + r) * 3 * WDIM + hoff + d4);
        __nv_bfloat162 h0, l0, h1, l1;
        split2(v.x * 0.125f, v.y * 0.125f, h0, l0);
        split2(v.z * 0.125f, v.w * 0.125f, h1, l1);
        uint32_t o = SWZ128((uint32_t)(r * 128 + d4 * 2));
        *(__nv_bfloat162*)(smraw + o)            = h0;
        *(__nv_bfloat162*)(smraw + o + 4)        = h1;
        *(__nv_bfloat162*)(smraw + 8192 + o)     = l0;
        *(__nv_bfloat162*)(smraw + 8192 + o + 4) = l1;
    }

    // persistent state
    float m0r = -1e30f, m1r = -1e30f, l0r = 0.f, l1r = 0.f;
    float O[8][4];
    #pragma unroll
    for (int nb = 0; nb < 8; nb++)
        #pragma unroll
        for (int q = 0; q < 4; q++) O[nb][q] = 0.f;

    const int a_row = wid * 16 + (lane & 15);
    const int a_k8 = (lane >> 4) << 3;
    const int b_r  = (lane & 7) + ((lane & 16) ? 8 : 0);
    const int b_k8 = lane & 8;

    for (int kt = 0; kt < SEQ / 64; kt++) {
        __syncthreads();
        // ---- load K (split) + V (split + transpose) for keys kt*64.. ----
        for (int e = tid; e < 1024; e += 128) {
            int r = e >> 4, d4 = (e & 15) << 2;
            size_t gbase = rowbase + (size_t)(kt * 64 + r) * 3 * WDIM + hoff + d4;
            float4 kv = *(const float4*)(qkv + gbase + WDIM);
            __nv_bfloat162 h0, l0, h1, l1;
            split2(kv.x, kv.y, h0, l0);
            split2(kv.z, kv.w, h1, l1);
            uint32_t o = SWZ128((uint32_t)(r * 128 + d4 * 2));
            *(__nv_bfloat162*)(smraw + 16384 + o)     = h0;
            *(__nv_bfloat162*)(smraw + 16384 + o + 4) = h1;
            *(__nv_bfloat162*)(smraw + 24576 + o)     = l0;
            *(__nv_bfloat162*)(smraw + 24576 + o + 4) = l1;
            float4 vv = *(const float4*)(qkv + gbase + 2 * WDIM);
            const float* vp = &vv.x;
            #pragma unroll
            for (int i = 0; i < 4; i++) {
                float x = vp[i];
                __nv_bfloat16 hh = __float2bfloat16(x);
                __nv_bfloat16 ll = __float2bfloat16(x - __bfloat162float(hh));
                uint32_t ov = SWZ128((uint32_t)((d4 + i) * 128 + r * 2));
                *(__nv_bfloat16*)(smraw + 32768 + ov) = hh;
                *(__nv_bfloat16*)(smraw + 40960 + ov) = ll;
            }
        }
        __syncthreads();

        // ---- S = QK^T (3-term split) ----
        float S[8][4];
        #pragma unroll
        for (int nb = 0; nb < 8; nb++)
            #pragma unroll
            for (int q = 0; q < 4; q++) S[nb][q] = 0.f;

        #pragma unroll
        for (int kk = 0; kk < 4; kk++) {
            uint32_t aoff = SWZ128((uint32_t)(a_row * 128 + (kk * 16 + a_k8) * 2));
            uint32_t aH[4], aL[4];
            ldsm4(aH, sQh + aoff);
            ldsm4(aL, sQl + aoff);
            uint32_t bh[8][2], bl[8][2];
            #pragma unroll
            for (int pr = 0; pr < 4; pr++) {
                uint32_t boff = SWZ128((uint32_t)((pr * 16 + b_r) * 128 + (kk * 16 + b_k8) * 2));
                uint32_t r4[4];
                ldsm4(r4, sKh + boff);
                bh[pr * 2][0] = r4[0]; bh[pr * 2][1] = r4[1];
                bh[pr * 2 + 1][0] = r4[2]; bh[pr * 2 + 1][1] = r4[3];
                ldsm4(r4, sKl + boff);
                bl[pr * 2][0] = r4[0]; bl[pr * 2][1] = r4[1];
                bl[pr * 2 + 1][0] = r4[2]; bl[pr * 2 + 1][1] = r4[3];
            }
            #pragma unroll
            for (int nb = 0; nb < 8; nb++) {
                mma16816(S[nb], aH, bh[nb]);
                mma16816(S[nb], aH, bl[nb]);
                mma16816(S[nb], aL, bh[nb]);
            }
        }

        // ---- online softmax (rows: r0 = lane>>2, r1 = r0+8) ----
        float mx0 = -1e30f, mx1 = -1e30f;
        #pragma unroll
        for (int nb = 0; nb < 8; nb++) {
            mx0 = fmaxf(mx0, fmaxf(S[nb][0], S[nb][1]));
            mx1 = fmaxf(mx1, fmaxf(S[nb][2], S[nb][3]));
        }
        mx0 = fmaxf(mx0, __shfl_xor_sync(0xffffffffu, mx0, 1));
        mx0 = fmaxf(mx0, __shfl_xor_sync(0xffffffffu, mx0, 2));
        mx1 = fmaxf(mx1, __shfl_xor_sync(0xffffffffu, mx1, 1));
        mx1 = fmaxf(mx1, __shfl_xor_sync(0xffffffffu, mx1, 2));
        float nm0 = fmaxf(m0r, mx0), nm1 = fmaxf(m1r, mx1);
        float al0 = __expf(m0r - nm0), al1 = __expf(m1r - nm1);
        m0r = nm0; m1r = nm1;
        float sum0 = 0.f, sum1 = 0.f;
        #pragma unroll
        for (int nb = 0; nb < 8; nb++) {
            S[nb][0] = __expf(S[nb][0] - nm0); sum0 += S[nb][0];
            S[nb][1] = __expf(S[nb][1] - nm0); sum0 += S[nb][1];
            S[nb][2] = __expf(S[nb][2] - nm1); sum1 += S[nb][2];
            S[nb][3] = __expf(S[nb][3] - nm1); sum1 += S[nb][3];
        }
        sum0 += __shfl_xor_sync(0xffffffffu, sum0, 1);
        sum0 += __shfl_xor_sync(0xffffffffu, sum0, 2);
        sum1 += __shfl_xor_sync(0xffffffffu, sum1, 1);
        sum1 += __shfl_xor_sync(0xffffffffu, sum1, 2);
        l0r = l0r * al0 + sum0;
        l1r = l1r * al1 + sum1;
        #pragma unroll
        for (int nb = 0; nb < 8; nb++) {
            O[nb][0] *= al0; O[nb][1] *= al0;
            O[nb][2] *= al1; O[nb][3] *= al1;
        }

        // ---- O += P * V (3-term split), P packed in-register as A-frags ----
        #pragma unroll
        for (int kk = 0; kk < 4; kk++) {
            uint32_t ph[4], pl[4];
            {
                __nv_bfloat162 h2, l2;
                split2(S[2*kk][0],   S[2*kk][1],   h2, l2); ph[0] = b2u(h2); pl[0] = b2u(l2);
                split2(S[2*kk][2],   S[2*kk][3],   h2, l2); ph[1] = b2u(h2); pl[1] = b2u(l2);
                split2(S[2*kk+1][0], S[2*kk+1][1], h2, l2); ph[2] = b2u(h2); pl[2] = b2u(l2);
                split2(S[2*kk+1][2], S[2*kk+1][3], h2, l2); ph[3] = b2u(h2); pl[3] = b2u(l2);
            }
            uint32_t bh[8][2], bl[8][2];
            #pragma unroll
            for (int pr = 0; pr < 4; pr++) {
                uint32_t boff = SWZ128((uint32_t)((pr * 16 + b_r) * 128 + (kk * 16 + b_k8) * 2));
                uint32_t r4[4];
                ldsm4(r4, sVh + boff);
                bh[pr * 2][0] = r4[0]; bh[pr * 2][1] = r4[1];
                bh[pr * 2 + 1][0] = r4[2]; bh[pr * 2 + 1][1] = r4[3];
                ldsm4(r4, sVl + boff);
                bl[pr * 2][0] = r4[0]; bl[pr * 2][1] = r4[1];
                bl[pr * 2 + 1][0] = r4[2]; bl[pr * 2 + 1][1] = r4[3];
            }
            #pragma unroll
            for (int nb = 0; nb < 8; nb++) {
                mma16816(O[nb], ph, bh[nb]);
                mma16816(O[nb], pl, bh[nb]);
                mma16816(O[nb], ph, bl[nb]);
            }
        }
    }

    // ---- epilogue: normalize + split-write ctx ----
    const float i0 = 1.f / l0r, i1 = 1.f / l1r;
    const int r0 = b * SEQ + qt * 64 + wid * 16 + (lane >> 2);
    const int c0 = hoff + 2 * (lane & 3);
    #pragma unroll
    for (int nb = 0; nb < 8; nb++) {
        const int col = c0 + nb * 8;
        __nv_bfloat162 h2, l2;
        split2(O[nb][0] * i0, O[nb][1] * i0, h2, l2);
        *(__nv_bfloat162*)(ctx_h + (size_t)r0 * WDIM + col) = h2;
        *(__nv_bfloat162*)(ctx_l + (size_t)r0 * WDIM + col) = l2;
        split2(O[nb][2] * i1, O[nb][3] * i1, h2, l2);
        *(__nv_bfloat162*)(ctx_h + (size_t)(r0 + 8) * WDIM + col) = h2;
        *(__nv_bfloat162*)(ctx_l + (size_t)(r0 + 8) * WDIM + col) = l2;
    }
}

// ---------------------------------------------------------------------------
// Residual add + LayerNorm; optionally also writes split-bf16 output.
// ---------------------------------------------------------------------------
template<int SPLIT>
__global__ void __launch_bounds__(256) ln_residual(
    const float* __restrict__ x, const float* __restrict__ r,
    const float* __restrict__ gamma, const float* __restrict__ beta,
    float* __restrict__ out, __nv_bfloat16* __restrict__ oh, __nv_bfloat16* __restrict__ ol)
{
    __shared__ float red[2][8];
    __shared__ float stats[2];
    const int row = blockIdx.x, tid = threadIdx.x;
    const size_t base = (size_t)row * WDIM;
    float v[4];
    float s = 0.f, sq = 0.f;
    #pragma unroll
    for (int c = 0; c < 4; c++) {
        int w = tid + c * 256;
        float a = x[base + w] + r[base + w];
        v[c] = a; s += a; sq += a * a;
    }
    #pragma unroll
    for (int off = 16; off; off >>= 1) {
        s  += __shfl_xor_sync(0xffffffffu, s, off);
        sq += __shfl_xor_sync(0xffffffffu, sq, off);
    }
    int lane = tid & 31, wid = tid >> 5;
    if (lane == 0) { red[0][wid] = s; red[1][wid] = sq; }
    __syncthreads();
    if (tid == 0) {
        float ts = 0.f, tq = 0.f;
        #pragma unroll
        for (int w = 0; w < 8; w++) { ts += red[0][w]; tq += red[1][w]; }
        float mean = ts * (1.f / WDIM);
        float var  = tq * (1.f / WDIM) - mean * mean;
        stats[0] = mean;
        stats[1] = rsqrtf(var + 1e-5f);
    }
    __syncthreads();
    float mean = stats[0], rstd = stats[1];
    #pragma unroll
    for (int c = 0; c < 4; c++) {
        int w = tid + c * 256;
        float o = (v[c] - mean) * rstd * gamma[w] + beta[w];
        out[base + w] = o;
        if (SPLIT) {
            __nv_bfloat16 hh = __float2bfloat16(o);
            oh[base + w] = hh;
            ol[base + w] = __float2bfloat16(o - __bfloat162float(hh));
        }
    }
}

// ---------------------------------------------------------------------------
// Topic kernel
// ---------------------------------------------------------------------------
__global__ void __launch_bounds__(256) topic_kernel(
    const float* __restrict__ hidden, const int* __restrict__ in_ids,
    const int* __restrict__ res_ids, const float* __restrict__ tw,
    const float* __restrict__ tb, const float* __restrict__ tt,
    float* __restrict__ ue)
{
    __shared__ float mp[WDIM];
    __shared__ float logits[64];
    __shared__ float probs[64];
    __shared__ int sid[SEQ];
    const int tid = threadIdx.x;
    const int g = blockIdx.x, b = blockIdx.y;

    for (int s = tid; s < SEQ; s += 256) {
        int id;
        if (g < 6) id = (s < S_IN) ? in_ids[b * S_IN + s] : 0;
        else       id = (s >= S_IN) ? res_ids[b * 129 + (s - S_IN + 1)] : 0;
        sid[s] = id;
    }
    __syncthreads();

    const int gid = (g < 6) ? (g + 1) : 1;
    float acc[4] = {0.f, 0.f, 0.f, 0.f};
    for (int s = 0; s < SEQ; s++) {
        if (sid[s] == gid) {
            const float* hr = hidden + (size_t)(b * SEQ + s) * WDIM;
            #pragma unroll
            for (int c = 0; c < 4; c++)
                acc[c] = fmaxf(acc[c], hr[tid + c * 256]);
        }
    }
    #pragma unroll
    for (int c = 0; c < 4; c++) mp[tid + c * 256] = acc[c];
    __syncthreads();

    int lane = tid & 31, wid = tid >> 5;
    for (int t = wid; t < NTOP; t += 8) {
        const float* wrow = tw + (size_t)t * WDIM;
        float d = 0.f;
        for (int w = lane; w < WDIM; w += 32) d += mp[w] * wrow[w];
        #pragma unroll
        for (int off = 16; off; off >>= 1)
            d += __shfl_xor_sync(0xffffffffu, d, off);
        if (lane == 0) logits[t] = d + tb[t];
    }
    __syncthreads();

    if (tid < 32) {
        float mval = -1e30f;
        for (int t = tid; t < NTOP; t += 32) mval = fmaxf(mval, logits[t]);
        #pragma unroll
        for (int off = 16; off; off >>= 1)
            mval = fmaxf(mval, __shfl_xor_sync(0xffffffffu, mval, off));
        float ssum = 0.f;
        for (int t = tid; t < NTOP; t += 32) {
            float p = __expf(logits[t] - mval);
            probs[t] = p; ssum += p;
        }
        #pragma unroll
        for (int off = 16; off; off >>= 1)
            ssum += __shfl_xor_sync(0xffffffffu, ssum, off);
        float inv = 1.f / ssum;
        for (int t = tid; t < NTOP; t += 32) probs[t] *= inv;
    }
    __syncthreads();

    float uacc[4] = {0.f, 0.f, 0.f, 0.f};
    for (int t = 0; t < NTOP; t++) {
        float p = probs[t];
        const float* trow = tt + (size_t)t * WDIM;
        #pragma unroll
        for (int c = 0; c < 4; c++) uacc[c] += p * trow[tid + c * 256];
    }
    float* urow = ue + (size_t)(b * NGRP + g) * WDIM;
    #pragma unroll
    for (int c = 0; c < 4; c++) urow[tid + c * 256] = uacc[c];
}

// ---------------------------------------------------------------------------
// Final scatter-add
// ---------------------------------------------------------------------------
__global__ void __launch_bounds__(256) final_add(
    const float* __restrict__ inp, const int* __restrict__ in_ids,
    const int* __restrict__ res_ids, const float* __restrict__ ue,
    float* __restrict__ out)
{
    const int row = blockIdx.x, tid = threadIdx.x;
    const int b = row >> 9, s = row & 511;
    int g = 0; float mult = 0.f;
    if (s < S_IN) {
        int id = in_ids[b * S_IN + s];
        if (id > 0)      { g = id - 1;  mult = 1.f; }
        else if (id < 0) { g = -id - 1; mult = 2.f; }
    } else {
        int id = res_ids[b * 129 + (s - S_IN + 1)];
        g = 6;
        if (id > 0)      mult = 1.f;
        else if (id < 0) mult = 2.f;
    }
    const size_t base = (size_t)row * WDIM;
    const float* urow = ue + (size_t)(b * NGRP + g) * WDIM;
    #pragma unroll
    for (int c = 0; c < 4; c++) {
        int w = tid + c * 256;
        out[base + w] = inp[base + w] + mult * urow[w];
    }
}

// ---------------------------------------------------------------------------
// Launch
// ---------------------------------------------------------------------------
extern "C" void kernel_launch(void* const* d_in, const int* in_sizes, int n_in,
                              void* d_out, int out_size)
{
    const float* inp     = (const float*)d_in[0];
    const int*   in_ids  = (const int*)  d_in[1];
    const int*   res_ids = (const int*)  d_in[2];
    const float* Wqkv    = (const float*)d_in[3];
    const float* bqkv    = (const float*)d_in[4];
    const float* Wo      = (const float*)d_in[5];
    const float* bo      = (const float*)d_in[6];
    const float* ln1g    = (const float*)d_in[7];
    const float* ln1b    = (const float*)d_in[8];
    const float* W1      = (const float*)d_in[9];
    const float* b1      = (const float*)d_in[10];
    const float* W2      = (const float*)d_in[11];
    const float* b2      = (const float*)d_in[12];
    const float* ln2g    = (const float*)d_in[13];
    const float* ln2b    = (const float*)d_in[14];
    const float* tw      = (const float*)d_in[15];
    const float* tb      = (const float*)d_in[16];
    const float* tt      = (const float*)d_in[17];
    float* out = (float*)d_out;

    float *qkv, *tmp, *y, *hidden, *ue;
    cudaGetSymbolAddress((void**)&qkv,    g_qkv);
    cudaGetSymbolAddress((void**)&tmp,    g_tmp);
    cudaGetSymbolAddress((void**)&y,      g_y);
    cudaGetSymbolAddress((void**)&hidden, g_hidden);
    cudaGetSymbolAddress((void**)&ue,     g_ue);

    __nv_bfloat16 *inp_h, *inp_l, *ctx_h, *ctx_l, *yh, *yl, *ffh, *ffl;
    __nv_bfloat16 *wqkv_h, *wqkv_l, *wo_h, *wo_l, *w1_h, *w1_l, *w2_h, *w2_l;
    cudaGetSymbolAddress((void**)&inp_h,  g_inp_h);
    cudaGetSymbolAddress((void**)&inp_l,  g_inp_l);
    cudaGetSymbolAddress((void**)&ctx_h,  g_ctx_h);
    cudaGetSymbolAddress((void**)&ctx_l,  g_ctx_l);
    cudaGetSymbolAddress((void**)&yh,     g_yh);
    cudaGetSymbolAddress((void**)&yl,     g_yl);
    cudaGetSymbolAddress((void**)&ffh,    g_ffh);
    cudaGetSymbolAddress((void**)&ffl,    g_ffl);
    cudaGetSymbolAddress((void**)&wqkv_h, g_wqkv_h);
    cudaGetSymbolAddress((void**)&wqkv_l, g_wqkv_l);
    cudaGetSymbolAddress((void**)&wo_h,   g_wo_h);
    cudaGetSymbolAddress((void**)&wo_l,   g_wo_l);
    cudaGetSymbolAddress((void**)&w1_h,   g_w1_h);
    cudaGetSymbolAddress((void**)&w1_l,   g_w1_l);
    cudaGetSymbolAddress((void**)&w2_h,   g_w2_h);
    cudaGetSymbolAddress((void**)&w2_l,   g_w2_l);

    cudaFuncSetAttribute(attn_flash,
                         cudaFuncAttributeMaxDynamicSharedMemorySize, ATT_SMEM);
    cudaFuncSetAttribute(gemm_mma<0,1,0>,
                         cudaFuncAttributeMaxDynamicSharedMemorySize, GEMM_SMEM);
    cudaFuncSetAttribute(gemm_mma<1,0,1>,
                         cudaFuncAttributeMaxDynamicSharedMemorySize, GEMM_SMEM);

    // 0) fp32 -> split-bf16 conversions (inputs + weights)
    auto launch_split = [&](const float* s, __nv_bfloat16* h, __nv_bfloat16* l, size_t n) {
        int n4 = (int)(n / 4);
        split_f32<<<(n4 + 255) / 256, 256>>>(s, h, l, n4);
    };
    launch_split(inp,  inp_h,  inp_l,  (size_t)MTOT * WDIM);
    launch_split(Wqkv, wqkv_h, wqkv_l, (size_t)3 * WDIM * WDIM);
    launch_split(Wo,   wo_h,   wo_l,   (size_t)WDIM * WDIM);
    launch_split(W1,   w1_h,   w1_l,   (size_t)DFFDIM * WDIM);
    launch_split(W2,   w2_h,   w2_l,   (size_t)WDIM * DFFDIM);

    // 1) QKV projection: qkv = inp @ Wqkv^T + bqkv
    gemm_mma<0,1,0><<<dim3(3 * WDIM / 128, MTOT / 128), 256, GEMM_SMEM>>>(
        inp_h, inp_l, wqkv_h, wqkv_l, bqkv, qkv, nullptr, nullptr, 3 * WDIM, WDIM);
    // 2) Attention (tensor split-bf16) -> split ctx
    attn_flash<<<dim3(SEQ / 64, HEADS, BATCH), 128, ATT_SMEM>>>(qkv, ctx_h, ctx_l);
    // 3) O projection: tmp = ctx @ Wo^T + bo
    gemm_mma<0,1,0><<<dim3(WDIM / 128, MTOT / 128), 256, GEMM_SMEM>>>(
        ctx_h, ctx_l, wo_h, wo_l, bo, tmp, nullptr, nullptr, WDIM, WDIM);
    // 4) LN1(inp + tmp) -> y (fp32 + split)
    ln_residual<1><<<MTOT, 256>>>(inp, tmp, ln1g, ln1b, y, yh, yl);
    // 5) FF1 + GELU -> split ff only
    gemm_mma<1,0,1><<<dim3(DFFDIM / 128, MTOT / 128), 256, GEMM_SMEM>>>(
        yh, yl, w1_h, w1_l, b1, nullptr, ffh, ffl, DFFDIM, WDIM);
    // 6) FF2: tmp = ff @ W2^T + b2
    gemm_mma<0,1,0><<<dim3(WDIM / 128, MTOT / 128), 256, GEMM_SMEM>>>(
        ffh, ffl, w2_h, w2_l, b2, tmp, nullptr, nullptr, WDIM, DFFDIM);
    // 7) LN2(y + tmp) -> hidden
    ln_residual<0><<<MTOT, 256>>>(y, tmp, ln2g, ln2b, hidden, nullptr, nullptr);
    // 8) Topic embeddings
    topic_kernel<<<dim3(NGRP, BATCH), 256>>>(hidden, in_ids, res_ids, tw, tb, tt, ue);
    // 9) Final scatter-add
    final_add<<<MTOT, 256>>>(inp, in_ids, res_ids, ue, out);
}

// round 13
// speedup vs baseline: 4.1783x; 1.2018x over previous
#include <cuda_runtime.h>
#include <cuda_bf16.h>
#include <cuda_fp16.h>
#include <math.h>
#include <cstdint>

// ---------------------------------------------------------------------------
// Problem constants
// ---------------------------------------------------------------------------
#define BATCH   16
#define SEQ     512
#define S_IN    384
#define WDIM    1024
#define HEADS   16
#define DH      64
#define DFFDIM  4096
#define NTOP    50
#define NGRP    7
#define MTOT    (BATCH*SEQ)          // 8192 rows

// ---------------------------------------------------------------------------
// Scratch (static device globals). 16-bit buffers are raw uint16_t and hold
// bf16 or fp16 depending on pipeline stage.
// ---------------------------------------------------------------------------
__device__ __align__(256) float g_qkv[(size_t)MTOT * 3 * WDIM];
__device__ __align__(256) float g_tmp[(size_t)MTOT * WDIM];
__device__ __align__(256) float g_y[(size_t)MTOT * WDIM];
__device__ __align__(256) float g_hidden[(size_t)MTOT * WDIM];
__device__ __align__(256) float g_ue[(size_t)BATCH * NGRP * WDIM];

__device__ __align__(256) uint16_t g_inp_h[(size_t)MTOT * WDIM];
__device__ __align__(256) uint16_t g_inp_l[(size_t)MTOT * WDIM];
__device__ __align__(256) uint16_t g_ctx_h[(size_t)MTOT * WDIM];
__device__ __align__(256) uint16_t g_ctx_l[(size_t)MTOT * WDIM];
__device__ __align__(256) uint16_t g_yh[(size_t)MTOT * WDIM];      // fp16 (hi only)
__device__ __align__(256) uint16_t g_ffh[(size_t)MTOT * DFFDIM];   // fp16 (hi only)
__device__ __align__(256) uint16_t g_wqkv_h[(size_t)3 * WDIM * WDIM];
__device__ __align__(256) uint16_t g_wqkv_l[(size_t)3 * WDIM * WDIM];
__device__ __align__(256) uint16_t g_wo_h[(size_t)WDIM * WDIM];
__device__ __align__(256) uint16_t g_wo_l[(size_t)WDIM * WDIM];
__device__ __align__(256) uint16_t g_w1_h[(size_t)DFFDIM * WDIM];  // fp16
__device__ __align__(256) uint16_t g_w1_l[(size_t)DFFDIM * WDIM];  // fp16
__device__ __align__(256) uint16_t g_w2_h[(size_t)WDIM * DFFDIM];  // fp16
__device__ __align__(256) uint16_t g_w2_l[(size_t)WDIM * DFFDIM];  // fp16

__device__ __forceinline__ float gelu_exact(float x) {
    return 0.5f * x * (1.0f + erff(x * 0.70710678118654752f));
}

// ---------------------------------------------------------------------------
// PTX helpers
// ---------------------------------------------------------------------------
__device__ __forceinline__ uint32_t smem_u32(const void* p) {
    uint32_t a;
    asm("{ .reg .u64 t; cvta.to.shared.u64 t, %1; cvt.u32.u64 %0, t; }"
        : "=r"(a) : "l"(p));
    return a;
}
#define SWZ128(off) ((off) ^ (((off) >> 3) & 0x70))

#define CP16(dst, src) \
    asm volatile("cp.async.cg.shared.global [%0], [%1], 16;" \
        :: "r"(dst), "l"(__cvta_generic_to_global(src)) : "memory")
#define CP_COMMIT() asm volatile("cp.async.commit_group;" ::: "memory")
#define CP_WAIT1() asm volatile("cp.async.wait_group 1;" ::: "memory")
#define CP_WAIT0() asm volatile("cp.async.wait_group 0;" ::: "memory")

__device__ __forceinline__ void ldsm4(uint32_t r[4], uint32_t addr) {
    asm volatile("ldmatrix.sync.aligned.m8n8.x4.shared.b16 {%0,%1,%2,%3}, [%4];"
        : "=r"(r[0]), "=r"(r[1]), "=r"(r[2]), "=r"(r[3]) : "r"(addr));
}

__device__ __forceinline__ void mma_bf16(float d[4], const uint32_t a[4], const uint32_t b[2]) {
    asm volatile(
        "mma.sync.aligned.m16n8k16.row.col.f32.bf16.bf16.f32 "
        "{%0,%1,%2,%3}, {%4,%5,%6,%7}, {%8,%9}, {%0,%1,%2,%3};"
        : "+f"(d[0]), "+f"(d[1]), "+f"(d[2]), "+f"(d[3])
        : "r"(a[0]), "r"(a[1]), "r"(a[2]), "r"(a[3]), "r"(b[0]), "r"(b[1]));
}
__device__ __forceinline__ void mma_f16(float d[4], const uint32_t a[4], const uint32_t b[2]) {
    asm volatile(
        "mma.sync.aligned.m16n8k16.row.col.f32.f16.f16.f32 "
        "{%0,%1,%2,%3}, {%4,%5,%6,%7}, {%8,%9}, {%0,%1,%2,%3};"
        : "+f"(d[0]), "+f"(d[1]), "+f"(d[2]), "+f"(d[3])
        : "r"(a[0]), "r"(a[1]), "r"(a[2]), "r"(a[3]), "r"(b[0]), "r"(b[1]));
}

// ---------------------------------------------------------------------------
// fp32 -> (hi, lo) splits
// ---------------------------------------------------------------------------
__device__ __forceinline__ void split2(float a, float b, __nv_bfloat162& h2, __nv_bfloat162& l2) {
    __nv_bfloat16 ah = __float2bfloat16(a), bh = __float2bfloat16(b);
    h2.x = ah; h2.y = bh;
    l2.x = __float2bfloat16(a - __bfloat162float(ah));
    l2.y = __float2bfloat16(b - __bfloat162float(bh));
}
__device__ __forceinline__ uint32_t b2u(__nv_bfloat162 v) {
    union { __nv_bfloat162 b; uint32_t u; } c; c.b = v; return c.u;
}

// HALF=0: bf16 hi/lo.  HALF=1: fp16 hi/lo.
template<int HALF>
__global__ void __launch_bounds__(256) split_f32(
    const float* __restrict__ src, uint16_t* __restrict__ hi,
    uint16_t* __restrict__ lo, int n4)
{
    int i = blockIdx.x * 256 + threadIdx.x;
    if (i >= n4) return;
    float4 v = ((const float4*)src)[i];
    if (HALF) {
        __half a0 = __float2half(v.x), a1 = __float2half(v.y);
        __half a2 = __float2half(v.z), a3 = __float2half(v.w);
        ((__half2*)hi)[2 * i]     = __halves2half2(a0, a1);
        ((__half2*)hi)[2 * i + 1] = __halves2half2(a2, a3);
        ((__half2*)lo)[2 * i]     = __halves2half2(
            __float2half(v.x - __half2float(a0)), __float2half(v.y - __half2float(a1)));
        ((__half2*)lo)[2 * i + 1] = __halves2half2(
            __float2half(v.z - __half2float(a2)), __float2half(v.w - __half2float(a3)));
    } else {
        __nv_bfloat162 h0, l0, h1, l1;
        split2(v.x, v.y, h0, l0);
        split2(v.z, v.w, h1, l1);
        ((__nv_bfloat162*)hi)[2 * i]     = h0;
        ((__nv_bfloat162*)hi)[2 * i + 1] = h1;
        ((__nv_bfloat162*)lo)[2 * i]     = l0;
        ((__nv_bfloat162*)lo)[2 * i + 1] = l1;
    }
}

// ---------------------------------------------------------------------------
// mma.sync split GEMM: C[M,N] = A[M,K] @ B[N,K]^T + bias
// NTERMS=3 (bf16): Ah*Bh + Ah*Bl + Al*Bh.   NTERMS=2 (fp16): Ah*Bh + Ah*Bl.
// CTA 128x128, 8 warps (2M x 4N), 3-stage cp.async ring, single barrier/chunk.
// WSPLIT: 0 none, 1 hi+lo, 2 hi only.
// ---------------------------------------------------------------------------
#define GEMM_SMEM (1024 + 3 * 32768)

template<int DO_GELU, int WF32, int WSPLIT, int NTERMS, int HALF>
__global__ void __launch_bounds__(256, 2) gemm_mma(
    const uint16_t* __restrict__ Ahi, const uint16_t* __restrict__ Alo,
    const uint16_t* __restrict__ Bhi, const uint16_t* __restrict__ Blo,
    const float* __restrict__ bias,
    float* __restrict__ Cf, uint16_t* __restrict__ Chi, uint16_t* __restrict__ Clo,
    int N, int K)
{
    extern __shared__ char smraw[];
    const uint32_t sb = (smem_u32(smraw) + 1023u) & ~1023u;
    const int tid = threadIdx.x;
    const int wid = tid >> 5, lane = tid & 31;
    const int wm = wid >> 2, wn = wid & 3;      // 2 x 4 warp grid
    const int m0 = blockIdx.y << 7, n0 = blockIdx.x << 7;
    const int KC = K >> 6;
    const int NC = NTERMS * KC;

    auto load_chunk = [&](int c, int s) {
        const int seg = c / KC;
        const int k0 = (c - seg * KC) << 6;
        const uint16_t* As = (seg == 2) ? Alo : Ahi;
        const uint16_t* Bs = (seg == 1) ? Blo : Bhi;
        const uint32_t stA = sb + s * 32768;
        const uint32_t stB = stA + 16384;
        #pragma unroll
        for (int j = 0; j < 4; j++) {
            int i = tid + (j << 8);                 // 0..1023
            int r = i >> 3, cc = i & 7;
            uint32_t off = SWZ128((uint32_t)(r * 128 + cc * 16));
            CP16(stA + off, As + (size_t)(m0 + r) * K + k0 + (cc << 3));
        }
        #pragma unroll
        for (int j = 0; j < 4; j++) {
            int i = tid + (j << 8);
            int r = i >> 3, cc = i & 7;
            uint32_t off = SWZ128((uint32_t)(r * 128 + cc * 16));
            CP16(stB + off, Bs + (size_t)(n0 + r) * K + k0 + (cc << 3));
        }
        CP_COMMIT();
    };

    load_chunk(0, 0);
    load_chunk(1, 1);

    float acc[4][4][4];
    #pragma unroll
    for (int mi = 0; mi < 4; mi++)
        #pragma unroll
        for (int nj = 0; nj < 4; nj++)
            #pragma unroll
            for (int q = 0; q < 4; q++) acc[mi][nj][q] = 0.f;

    const int a_row = wm * 64 + (lane & 15);
    const int a_kc8 = (lane >> 4) << 3;             // 0 or 8
    const int b_row = wn * 32 + (lane & 7) + ((lane & 16) ? 8 : 0);
    const int b_kc8 = (lane & 8);                   // 0 or 8

    for (int c = 0; c < NC; c++) {
        if (c < NC - 1) CP_WAIT1(); else CP_WAIT0();
        __syncthreads();        // single barrier: also orders prev reads vs next writes
        if (c + 2 < NC) load_chunk(c + 2, (c + 2) % 3);

        const uint32_t stA = sb + (c % 3) * 32768;
        const uint32_t stB = stA + 16384;
        #pragma unroll
        for (int kk = 0; kk < 4; kk++) {
            const int k0 = kk << 4;
            uint32_t a[4][4];
            #pragma unroll
            for (int mi = 0; mi < 4; mi++) {
                uint32_t off = (uint32_t)((a_row + mi * 16) * 128 + (k0 + a_kc8) * 2);
                ldsm4(a[mi], stA + SWZ128(off));
            }
            uint32_t b[4][2];
            #pragma unroll
            for (int pr = 0; pr < 2; pr++) {
                uint32_t r4[4];
                uint32_t off = (uint32_t)((b_row + pr * 16) * 128 + (k0 + b_kc8) * 2);
                ldsm4(r4, stB + SWZ128(off));
                b[pr * 2][0] = r4[0]; b[pr * 2][1] = r4[1];
                b[pr * 2 + 1][0] = r4[2]; b[pr * 2 + 1][1] = r4[3];
            }
            #pragma unroll
            for (int mi = 0; mi < 4; mi++)
                #pragma unroll
                for (int nj = 0; nj < 4; nj++) {
                    if (HALF) mma_f16(acc[mi][nj], a[mi], b[nj]);
                    else      mma_bf16(acc[mi][nj], a[mi], b[nj]);
                }
        }
    }
    __syncthreads();   // protect smem reuse vs epilogue (none) / tail exit order

    const int r_base = m0 + wm * 64 + (lane >> 2);
    const int c_base = n0 + wn * 32 + 2 * (lane & 3);
    #pragma unroll
    for (int nj = 0; nj < 4; nj++) {
        const int col = c_base + nj * 8;
        const float b0 = bias[col], b1 = bias[col + 1];
        #pragma unroll
        for (int mi = 0; mi < 4; mi++) {
            #pragma unroll
            for (int h = 0; h < 2; h++) {
                const int row = r_base + mi * 16 + h * 8;
                float x0 = acc[mi][nj][2 * h]     + b0;
                float x1 = acc[mi][nj][2 * h + 1] + b1;
                if (DO_GELU) { x0 = gelu_exact(x0); x1 = gelu_exact(x1); }
                if (WF32) {
                    *(float2*)(Cf + (size_t)row * N + col) = make_float2(x0, x1);
                }
                if (WSPLIT) {
                    if (HALF) {
                        __half h0c = __float2half(x0), h1c = __float2half(x1);
                        *(__half2*)((__half*)Chi + (size_t)row * N + col) = __halves2half2(h0c, h1c);
                        if (WSPLIT == 1) {
                            *(__half2*)((__half*)Clo + (size_t)row * N + col) = __halves2half2(
                                __float2half(x0 - __half2float(h0c)),
                                __float2half(x1 - __half2float(h1c)));
                        }
                    } else {
                        __nv_bfloat162 h2, l2;
                        split2(x0, x1, h2, l2);
                        *(__nv_bfloat162*)((__nv_bfloat16*)Chi + (size_t)row * N + col) = h2;
                        if (WSPLIT == 1)
                            *(__nv_bfloat162*)((__nv_bfloat16*)Clo + (size_t)row * N + col) = l2;
                    }
                }
            }
        }
    }
}

// ---------------------------------------------------------------------------
// Flash attention, tensor-core split-bf16 (unchanged from R12 passing version)
// ---------------------------------------------------------------------------
#define ATT_SMEM 49152

__global__ void __launch_bounds__(128) attn_flash(
    const float* __restrict__ qkv,
    uint16_t* __restrict__ ctx_h16, uint16_t* __restrict__ ctx_l16)
{
    __nv_bfloat16* ctx_h = (__nv_bfloat16*)ctx_h16;
    __nv_bfloat16* ctx_l = (__nv_bfloat16*)ctx_l16;
    extern __shared__ char smraw[];
    const uint32_t sb = smem_u32(smraw);
    const uint32_t sQh = sb, sQl = sb + 8192;
    const uint32_t sKh = sb + 16384, sKl = sb + 24576;
    const uint32_t sVh = sb + 32768, sVl = sb + 40960;

    const int tid = threadIdx.x;
    const int wid = tid >> 5, lane = tid & 31;
    const int qt = blockIdx.x, h = blockIdx.y, b = blockIdx.z;
    const size_t rowbase = (size_t)b * SEQ * 3 * WDIM;
    const int hoff = h * DH;

    for (int e = tid; e < 1024; e += 128) {
        int r = e >> 4, d4 = (e & 15) << 2;
        float4 v = *(const float4*)(qkv + rowbase + (size_t)(qt * 64 + r) * 3 * WDIM + hoff + d4);
        __nv_bfloat162 h0, l0, h1, l1;
        split2(v.x * 0.125f, v.y * 0.125f, h0, l0);
        split2(v.z * 0.125f, v.w * 0.125f, h1, l1);
        uint32_t o = SWZ128((uint32_t)(r * 128 + d4 * 2));
        *(__nv_bfloat162*)(smraw + o)            = h0;
        *(__nv_bfloat162*)(smraw + o + 4)        = h1;
        *(__nv_bfloat162*)(smraw + 8192 + o)     = l0;
        *(__nv_bfloat162*)(smraw + 8192 + o + 4) = l1;
    }

    float m0r = -1e30f, m1r = -1e30f, l0r = 0.f, l1r = 0.f;
    float O[8][4];
    #pragma unroll
    for (int nb = 0; nb < 8; nb++)
        #pragma unroll
        for (int q = 0; q < 4; q++) O[nb][q] = 0.f;

    const int a_row = wid * 16 + (lane & 15);
    const int a_k8 = (lane >> 4) << 3;
    const int b_r  = (lane & 7) + ((lane & 16) ? 8 : 0);
    const int b_k8 = lane & 8;

    for (int kt = 0; kt < SEQ / 64; kt++) {
        __syncthreads();
        for (int e = tid; e < 1024; e += 128) {
            int r = e >> 4, d4 = (e & 15) << 2;
            size_t gbase = rowbase + (size_t)(kt * 64 + r) * 3 * WDIM + hoff + d4;
            float4 kv = *(const float4*)(qkv + gbase + WDIM);
            __nv_bfloat162 h0, l0, h1, l1;
            split2(kv.x, kv.y, h0, l0);
            split2(kv.z, kv.w, h1, l1);
            uint32_t o = SWZ128((uint32_t)(r * 128 + d4 * 2));
            *(__nv_bfloat162*)(smraw + 16384 + o)     = h0;
            *(__nv_bfloat162*)(smraw + 16384 + o + 4) = h1;
            *(__nv_bfloat162*)(smraw + 24576 + o)     = l0;
            *(__nv_bfloat162*)(smraw + 24576 + o + 4) = l1;
            float4 vv = *(const float4*)(qkv + gbase + 2 * WDIM);
            const float* vp = &vv.x;
            #pragma unroll
            for (int i = 0; i < 4; i++) {
                float x = vp[i];
                __nv_bfloat16 hh = __float2bfloat16(x);
                __nv_bfloat16 ll = __float2bfloat16(x - __bfloat162float(hh));
                uint32_t ov = SWZ128((uint32_t)((d4 + i) * 128 + r * 2));
                *(__nv_bfloat16*)(smraw + 32768 + ov) = hh;
                *(__nv_bfloat16*)(smraw + 40960 + ov) = ll;
            }
        }
        __syncthreads();

        float S[8][4];
        #pragma unroll
        for (int nb = 0; nb < 8; nb++)
            #pragma unroll
            for (int q = 0; q < 4; q++) S[nb][q] = 0.f;

        #pragma unroll
        for (int kk = 0; kk < 4; kk++) {
            uint32_t aoff = SWZ128((uint32_t)(a_row * 128 + (kk * 16 + a_k8) * 2));
            uint32_t aH[4], aL[4];
            ldsm4(aH, sQh + aoff);
            ldsm4(aL, sQl + aoff);
            uint32_t bh[8][2], bl[8][2];
            #pragma unroll
            for (int pr = 0; pr < 4; pr++) {
                uint32_t boff = SWZ128((uint32_t)((pr * 16 + b_r) * 128 + (kk * 16 + b_k8) * 2));
                uint32_t r4[4];
                ldsm4(r4, sKh + boff);
                bh[pr * 2][0] = r4[0]; bh[pr * 2][1] = r4[1];
                bh[pr * 2 + 1][0] = r4[2]; bh[pr * 2 + 1][1] = r4[3];
                ldsm4(r4, sKl + boff);
                bl[pr * 2][0] = r4[0]; bl[pr * 2][1] = r4[1];
                bl[pr * 2 + 1][0] = r4[2]; bl[pr * 2 + 1][1] = r4[3];
            }
            #pragma unroll
            for (int nb = 0; nb < 8; nb++) {
                mma_bf16(S[nb], aH, bh[nb]);
                mma_bf16(S[nb], aH, bl[nb]);
                mma_bf16(S[nb], aL, bh[nb]);
            }
        }

        float mx0 = -1e30f, mx1 = -1e30f;
        #pragma unroll
        for (int nb = 0; nb < 8; nb++) {
            mx0 = fmaxf(mx0, fmaxf(S[nb][0], S[nb][1]));
            mx1 = fmaxf(mx1, fmaxf(S[nb][2], S[nb][3]));
        }
        mx0 = fmaxf(mx0, __shfl_xor_sync(0xffffffffu, mx0, 1));
        mx0 = fmaxf(mx0, __shfl_xor_sync(0xffffffffu, mx0, 2));
        mx1 = fmaxf(mx1, __shfl_xor_sync(0xffffffffu, mx1, 1));
        mx1 = fmaxf(mx1, __shfl_xor_sync(0xffffffffu, mx1, 2));
        float nm0 = fmaxf(m0r, mx0), nm1 = fmaxf(m1r, mx1);
        float al0 = __expf(m0r - nm0), al1 = __expf(m1r - nm1);
        m0r = nm0; m1r = nm1;
        float sum0 = 0.f, sum1 = 0.f;
        #pragma unroll
        for (int nb = 0; nb < 8; nb++) {
            S[nb][0] = __expf(S[nb][0] - nm0); sum0 += S[nb][0];
            S[nb][1] = __expf(S[nb][1] - nm0); sum0 += S[nb][1];
            S[nb][2] = __expf(S[nb][2] - nm1); sum1 += S[nb][2];
            S[nb][3] = __expf(S[nb][3] - nm1); sum1 += S[nb][3];
        }
        sum0 += __shfl_xor_sync(0xffffffffu, sum0, 1);
        sum0 += __shfl_xor_sync(0xffffffffu, sum0, 2);
        sum1 += __shfl_xor_sync(0xffffffffu, sum1, 1);
        sum1 += __shfl_xor_sync(0xffffffffu, sum1, 2);
        l0r = l0r * al0 + sum0;
        l1r = l1r * al1 + sum1;
        #pragma unroll
        for (int nb = 0; nb < 8; nb++) {
            O[nb][0] *= al0; O[nb][1] *= al0;
            O[nb][2] *= al1; O[nb][3] *= al1;
        }

        #pragma unroll
        for (int kk = 0; kk < 4; kk++) {
            uint32_t ph[4], pl[4];
            {
                __nv_bfloat162 h2, l2;
                split2(S[2*kk][0],   S[2*kk][1],   h2, l2); ph[0] = b2u(h2); pl[0] = b2u(l2);
                split2(S[2*kk][2],   S[2*kk][3],   h2, l2); ph[1] = b2u(h2); pl[1] = b2u(l2);
                split2(S[2*kk+1][0], S[2*kk+1][1], h2, l2); ph[2] = b2u(h2); pl[2] = b2u(l2);
                split2(S[2*kk+1][2], S[2*kk+1][3], h2, l2); ph[3] = b2u(h2); pl[3] = b2u(l2);
            }
            uint32_t bh[8][2], bl[8][2];
            #pragma unroll
            for (int pr = 0; pr < 4; pr++) {
                uint32_t boff = SWZ128((uint32_t)((pr * 16 + b_r) * 128 + (kk * 16 + b_k8) * 2));
                uint32_t r4[4];
                ldsm4(r4, sVh + boff);
                bh[pr * 2][0] = r4[0]; bh[pr * 2][1] = r4[1];
                bh[pr * 2 + 1][0] = r4[2]; bh[pr * 2 + 1][1] = r4[3];
                ldsm4(r4, sVl + boff);
                bl[pr * 2][0] = r4[0]; bl[pr * 2][1] = r4[1];
                bl[pr * 2 + 1][0] = r4[2]; bl[pr * 2 + 1][1] = r4[3];
            }
            #pragma unroll
            for (int nb = 0; nb < 8; nb++) {
                mma_bf16(O[nb], ph, bh[nb]);
                mma_bf16(O[nb], pl, bh[nb]);
                mma_bf16(O[nb], ph, bl[nb]);
            }
        }
    }

    const float i0 = 1.f / l0r, i1 = 1.f / l1r;
    const int r0 = b * SEQ + qt * 64 + wid * 16 + (lane >> 2);
    const int c0 = hoff + 2 * (lane & 3);
    #pragma unroll
    for (int nb = 0; nb < 8; nb++) {
        const int col = c0 + nb * 8;
        __nv_bfloat162 h2, l2;
        split2(O[nb][0] * i0, O[nb][1] * i0, h2, l2);
        *(__nv_bfloat162*)(ctx_h + (size_t)r0 * WDIM + col) = h2;
        *(__nv_bfloat162*)(ctx_l + (size_t)r0 * WDIM + col) = l2;
        split2(O[nb][2] * i1, O[nb][3] * i1, h2, l2);
        *(__nv_bfloat162*)(ctx_h + (size_t)(r0 + 8) * WDIM + col) = h2;
        *(__nv_bfloat162*)(ctx_l + (size_t)(r0 + 8) * WDIM + col) = l2;
    }
}

// ---------------------------------------------------------------------------
// Residual add + LayerNorm. SPLIT: 0 none, 2 hi only (fp16 if HALF).
// ---------------------------------------------------------------------------
template<int SPLIT, int HALF>
__global__ void __launch_bounds__(256) ln_residual(
    const float* __restrict__ x, const float* __restrict__ r,
    const float* __restrict__ gamma, const float* __restrict__ beta,
    float* __restrict__ out, uint16_t* __restrict__ oh)
{
    __shared__ float red[2][8];
    __shared__ float stats[2];
    const int row = blockIdx.x, tid = threadIdx.x;
    const size_t base = (size_t)row * WDIM;
    float v[4];
    float s = 0.f, sq = 0.f;
    #pragma unroll
    for (int c = 0; c < 4; c++) {
        int w = tid + c * 256;
        float a = x[base + w] + r[base + w];
        v[c] = a; s += a; sq += a * a;
    }
    #pragma unroll
    for (int off = 16; off; off >>= 1) {
        s  += __shfl_xor_sync(0xffffffffu, s, off);
        sq += __shfl_xor_sync(0xffffffffu, sq, off);
    }
    int lane = tid & 31, wid = tid >> 5;
    if (lane == 0) { red[0][wid] = s; red[1][wid] = sq; }
    __syncthreads();
    if (tid == 0) {
        float ts = 0.f, tq = 0.f;
        #pragma unroll
        for (int w = 0; w < 8; w++) { ts += red[0][w]; tq += red[1][w]; }
        float mean = ts * (1.f / WDIM);
        float var  = tq * (1.f / WDIM) - mean * mean;
        stats[0] = mean;
        stats[1] = rsqrtf(var + 1e-5f);
    }
    __syncthreads();
    float mean = stats[0], rstd = stats[1];
    #pragma unroll
    for (int c = 0; c < 4; c++) {
        int w = tid + c * 256;
        float o = (v[c] - mean) * rstd * gamma[w] + beta[w];
        out[base + w] = o;
        if (SPLIT == 2) {
            if (HALF) ((__half*)oh)[base + w] = __float2half(o);
            else      ((__nv_bfloat16*)oh)[base + w] = __float2bfloat16(o);
        }
    }
}

// ---------------------------------------------------------------------------
// Topic kernel (unchanged)
// ---------------------------------------------------------------------------
__global__ void __launch_bounds__(256) topic_kernel(
    const float* __restrict__ hidden, const int* __restrict__ in_ids,
    const int* __restrict__ res_ids, const float* __restrict__ tw,
    const float* __restrict__ tb, const float* __restrict__ tt,
    float* __restrict__ ue)
{
    __shared__ float mp[WDIM];
    __shared__ float logits[64];
    __shared__ float probs[64];
    __shared__ int sid[SEQ];
    const int tid = threadIdx.x;
    const int g = blockIdx.x, b = blockIdx.y;

    for (int s = tid; s < SEQ; s += 256) {
        int id;
        if (g < 6) id = (s < S_IN) ? in_ids[b * S_IN + s] : 0;
        else       id = (s >= S_IN) ? res_ids[b * 129 + (s - S_IN + 1)] : 0;
        sid[s] = id;
    }
    __syncthreads();

    const int gid = (g < 6) ? (g + 1) : 1;
    float acc[4] = {0.f, 0.f, 0.f, 0.f};
    for (int s = 0; s < SEQ; s++) {
        if (sid[s] == gid) {
            const float* hr = hidden + (size_t)(b * SEQ + s) * WDIM;
            #pragma unroll
            for (int c = 0; c < 4; c++)
                acc[c] = fmaxf(acc[c], hr[tid + c * 256]);
        }
    }
    #pragma unroll
    for (int c = 0; c < 4; c++) mp[tid + c * 256] = acc[c];
    __syncthreads();

    int lane = tid & 31, wid = tid >> 5;
    for (int t = wid; t < NTOP; t += 8) {
        const float* wrow = tw + (size_t)t * WDIM;
        float d = 0.f;
        for (int w = lane; w < WDIM; w += 32) d += mp[w] * wrow[w];
        #pragma unroll
        for (int off = 16; off; off >>= 1)
            d += __shfl_xor_sync(0xffffffffu, d, off);
        if (lane == 0) logits[t] = d + tb[t];
    }
    __syncthreads();

    if (tid < 32) {
        float mval = -1e30f;
        for (int t = tid; t < NTOP; t += 32) mval = fmaxf(mval, logits[t]);
        #pragma unroll
        for (int off = 16; off; off >>= 1)
            mval = fmaxf(mval, __shfl_xor_sync(0xffffffffu, mval, off));
        float ssum = 0.f;
        for (int t = tid; t < NTOP; t += 32) {
            float p = __expf(logits[t] - mval);
            probs[t] = p; ssum += p;
        }
        #pragma unroll
        for (int off = 16; off; off >>= 1)
            ssum += __shfl_xor_sync(0xffffffffu, ssum, off);
        float inv = 1.f / ssum;
        for (int t = tid; t < NTOP; t += 32) probs[t] *= inv;
    }
    __syncthreads();

    float uacc[4] = {0.f, 0.f, 0.f, 0.f};
    for (int t = 0; t < NTOP; t++) {
        float p = probs[t];
        const float* trow = tt + (size_t)t * WDIM;
        #pragma unroll
        for (int c = 0; c < 4; c++) uacc[c] += p * trow[tid + c * 256];
    }
    float* urow = ue + (size_t)(b * NGRP + g) * WDIM;
    #pragma unroll
    for (int c = 0; c < 4; c++) urow[tid + c * 256] = uacc[c];
}

// ---------------------------------------------------------------------------
// Final scatter-add (unchanged)
// ---------------------------------------------------------------------------
__global__ void __launch_bounds__(256) final_add(
    const float* __restrict__ inp, const int* __restrict__ in_ids,
    const int* __restrict__ res_ids, const float* __restrict__ ue,
    float* __restrict__ out)
{
    const int row = blockIdx.x, tid = threadIdx.x;
    const int b = row >> 9, s = row & 511;
    int g = 0; float mult = 0.f;
    if (s < S_IN) {
        int id = in_ids[b * S_IN + s];
        if (id > 0)      { g = id - 1;  mult = 1.f; }
        else if (id < 0) { g = -id - 1; mult = 2.f; }
    } else {
        int id = res_ids[b * 129 + (s - S_IN + 1)];
        g = 6;
        if (id > 0)      mult = 1.f;
        else if (id < 0) mult = 2.f;
    }
    const size_t base = (size_t)row * WDIM;
    const float* urow = ue + (size_t)(b * NGRP + g) * WDIM;
    #pragma unroll
    for (int c = 0; c < 4; c++) {
        int w = tid + c * 256;
        out[base + w] = inp[base + w] + mult * urow[w];
    }
}

// ---------------------------------------------------------------------------
// Launch
// ---------------------------------------------------------------------------
extern "C" void kernel_launch(void* const* d_in, const int* in_sizes, int n_in,
                              void* d_out, int out_size)
{
    const float* inp     = (const float*)d_in[0];
    const int*   in_ids  = (const int*)  d_in[1];
    const int*   res_ids = (const int*)  d_in[2];
    const float* Wqkv    = (const float*)d_in[3];
    const float* bqkv    = (const float*)d_in[4];
    const float* Wo      = (const float*)d_in[5];
    const float* bo      = (const float*)d_in[6];
    const float* ln1g    = (const float*)d_in[7];
    const float* ln1b    = (const float*)d_in[8];
    const float* W1      = (const float*)d_in[9];
    const float* b1      = (const float*)d_in[10];
    const float* W2      = (const float*)d_in[11];
    const float* b2      = (const float*)d_in[12];
    const float* ln2g    = (const float*)d_in[13];
    const float* ln2b    = (const float*)d_in[14];
    const float* tw      = (const float*)d_in[15];
    const float* tb      = (const float*)d_in[16];
    const float* tt      = (const float*)d_in[17];
    float* out = (float*)d_out;

    float *qkv, *tmp, *y, *hidden, *ue;
    cudaGetSymbolAddress((void**)&qkv,    g_qkv);
    cudaGetSymbolAddress((void**)&tmp,    g_tmp);
    cudaGetSymbolAddress((void**)&y,      g_y);
    cudaGetSymbolAddress((void**)&hidden, g_hidden);
    cudaGetSymbolAddress((void**)&ue,     g_ue);

    uint16_t *inp_h, *inp_l, *ctx_h, *ctx_l, *yh, *ffh;
    uint16_t *wqkv_h, *wqkv_l, *wo_h, *wo_l, *w1_h, *w1_l, *w2_h, *w2_l;
    cudaGetSymbolAddress((void**)&inp_h,  g_inp_h);
    cudaGetSymbolAddress((void**)&inp_l,  g_inp_l);
    cudaGetSymbolAddress((void**)&ctx_h,  g_ctx_h);
    cudaGetSymbolAddress((void**)&ctx_l,  g_ctx_l);
    cudaGetSymbolAddress((void**)&yh,     g_yh);
    cudaGetSymbolAddress((void**)&ffh,    g_ffh);
    cudaGetSymbolAddress((void**)&wqkv_h, g_wqkv_h);
    cudaGetSymbolAddress((void**)&wqkv_l, g_wqkv_l);
    cudaGetSymbolAddress((void**)&wo_h,   g_wo_h);
    cudaGetSymbolAddress((void**)&wo_l,   g_wo_l);
    cudaGetSymbolAddress((void**)&w1_h,   g_w1_h);
    cudaGetSymbolAddress((void**)&w1_l,   g_w1_l);
    cudaGetSymbolAddress((void**)&w2_h,   g_w2_h);
    cudaGetSymbolAddress((void**)&w2_l,   g_w2_l);

    cudaFuncSetAttribute(attn_flash,
                         cudaFuncAttributeMaxDynamicSharedMemorySize, ATT_SMEM);
    cudaFuncSetAttribute(gemm_mma<0,1,0,3,0>,
                         cudaFuncAttributeMaxDynamicSharedMemorySize, GEMM_SMEM);
    cudaFuncSetAttribute(gemm_mma<1,0,2,2,1>,
                         cudaFuncAttributeMaxDynamicSharedMemorySize, GEMM_SMEM);
    cudaFuncSetAttribute(gemm_mma<0,1,0,2,1>,
                         cudaFuncAttributeMaxDynamicSharedMemorySize, GEMM_SMEM);

    // 0) fp32 -> split conversions: bf16 for inp/Wqkv/Wo, fp16 for W1/W2
    auto split_b = [&](const float* s, uint16_t* h, uint16_t* l, size_t n) {
        int n4 = (int)(n / 4);
        split_f32<0><<<(n4 + 255) / 256, 256>>>(s, h, l, n4);
    };
    auto split_h = [&](const float* s, uint16_t* h, uint16_t* l, size_t n) {
        int n4 = (int)(n / 4);
        split_f32<1><<<(n4 + 255) / 256, 256>>>(s, h, l, n4);
    };
    split_b(inp,  inp_h,  inp_l,  (size_t)MTOT * WDIM);
    split_b(Wqkv, wqkv_h, wqkv_l, (size_t)3 * WDIM * WDIM);
    split_b(Wo,   wo_h,   wo_l,   (size_t)WDIM * WDIM);
    split_h(W1,   w1_h,   w1_l,   (size_t)DFFDIM * WDIM);
    split_h(W2,   w2_h,   w2_l,   (size_t)WDIM * DFFDIM);

    // 1) QKV projection (bf16 3-term): qkv = inp @ Wqkv^T + bqkv
    gemm_mma<0,1,0,3,0><<<dim3(3 * WDIM / 128, MTOT / 128), 256, GEMM_SMEM>>>(
        inp_h, inp_l, wqkv_h, wqkv_l, bqkv, qkv, nullptr, nullptr, 3 * WDIM, WDIM);
    // 2) Attention (tensor split-bf16) -> split ctx
    attn_flash<<<dim3(SEQ / 64, HEADS, BATCH), 128, ATT_SMEM>>>(qkv, ctx_h, ctx_l);
    // 3) O projection (bf16 3-term): tmp = ctx @ Wo^T + bo
    gemm_mma<0,1,0,3,0><<<dim3(WDIM / 128, MTOT / 128), 256, GEMM_SMEM>>>(
        ctx_h, ctx_l, wo_h, wo_l, bo, tmp, nullptr, nullptr, WDIM, WDIM);
    // 4) LN1(inp + tmp) -> y (fp32) + yh (fp16 hi only)
    ln_residual<2,1><<<MTOT, 256>>>(inp, tmp, ln1g, ln1b, y, yh);
    // 5) FF1 + GELU (fp16 2-term): ff_hi = gelu(y @ W1^T + b1)
    gemm_mma<1,0,2,2,1><<<dim3(DFFDIM / 128, MTOT / 128), 256, GEMM_SMEM>>>(
        yh, nullptr, w1_h, w1_l, b1, nullptr, ffh, nullptr, DFFDIM, WDIM);
    // 6) FF2 (fp16 2-term): tmp = ff @ W2^T + b2
    gemm_mma<0,1,0,2,1><<<dim3(WDIM / 128, MTOT / 128), 256, GEMM_SMEM>>>(
        ffh, nullptr, w2_h, w2_l, b2, tmp, nullptr, nullptr, WDIM, DFFDIM);
    // 7) LN2(y + tmp) -> hidden
    ln_residual<0,0><<<MTOT, 256>>>(y, tmp, ln2g, ln2b, hidden, nullptr);
    // 8) Topic embeddings
    topic_kernel<<<dim3(NGRP, BATCH), 256>>>(hidden, in_ids, res_ids, tw, tb, tt, ue);
    // 9) Final scatter-add
    final_add<<<MTOT, 256>>>(inp, in_ids, res_ids, ue, out);
}

// round 14
// speedup vs baseline: 4.8399x; 1.1583x over previous
#include <cuda_runtime.h>
#include <cuda_bf16.h>
#include <cuda_fp16.h>
#include <math.h>
#include <cstdint>

// ---------------------------------------------------------------------------
// Problem constants
// ---------------------------------------------------------------------------
#define BATCH   16
#define SEQ     512
#define S_IN    384
#define WDIM    1024
#define HEADS   16
#define DH      64
#define DFFDIM  4096
#define NTOP    50
#define NGRP    7
#define MTOT    (BATCH*SEQ)          // 8192 rows

// ---------------------------------------------------------------------------
// Scratch (static device globals). All 16-bit buffers hold fp16.
// ---------------------------------------------------------------------------
__device__ __align__(256) float g_qkv[(size_t)MTOT * 3 * WDIM];
__device__ __align__(256) float g_tmp[(size_t)MTOT * WDIM];
__device__ __align__(256) float g_y[(size_t)MTOT * WDIM];
__device__ __align__(256) float g_hidden[(size_t)MTOT * WDIM];
__device__ __align__(256) float g_ue[(size_t)BATCH * NGRP * WDIM];

__device__ __align__(256) uint16_t g_inp_h[(size_t)MTOT * WDIM];
__device__ __align__(256) uint16_t g_ctx_h[(size_t)MTOT * WDIM];
__device__ __align__(256) uint16_t g_yh[(size_t)MTOT * WDIM];
__device__ __align__(256) uint16_t g_ffh[(size_t)MTOT * DFFDIM];
__device__ __align__(256) uint16_t g_wqkv_h[(size_t)3 * WDIM * WDIM];
__device__ __align__(256) uint16_t g_wqkv_l[(size_t)3 * WDIM * WDIM];
__device__ __align__(256) uint16_t g_wo_h[(size_t)WDIM * WDIM];
__device__ __align__(256) uint16_t g_wo_l[(size_t)WDIM * WDIM];
__device__ __align__(256) uint16_t g_w1_h[(size_t)DFFDIM * WDIM];
__device__ __align__(256) uint16_t g_w1_l[(size_t)DFFDIM * WDIM];
__device__ __align__(256) uint16_t g_w2_h[(size_t)WDIM * DFFDIM];
__device__ __align__(256) uint16_t g_w2_l[(size_t)WDIM * DFFDIM];

__device__ __forceinline__ float gelu_exact(float x) {
    return 0.5f * x * (1.0f + erff(x * 0.70710678118654752f));
}

// ---------------------------------------------------------------------------
// PTX helpers
// ---------------------------------------------------------------------------
__device__ __forceinline__ uint32_t smem_u32(const void* p) {
    uint32_t a;
    asm("{ .reg .u64 t; cvta.to.shared.u64 t, %1; cvt.u32.u64 %0, t; }"
        : "=r"(a) : "l"(p));
    return a;
}
#define SWZ128(off) ((off) ^ (((off) >> 3) & 0x70))

#define CP16(dst, src) \
    asm volatile("cp.async.cg.shared.global [%0], [%1], 16;" \
        :: "r"(dst), "l"(__cvta_generic_to_global(src)) : "memory")
#define CP_COMMIT() asm volatile("cp.async.commit_group;" ::: "memory")
#define CP_WAIT1() asm volatile("cp.async.wait_group 1;" ::: "memory")
#define CP_WAIT0() asm volatile("cp.async.wait_group 0;" ::: "memory")

__device__ __forceinline__ void ldsm4(uint32_t r[4], uint32_t addr) {
    asm volatile("ldmatrix.sync.aligned.m8n8.x4.shared.b16 {%0,%1,%2,%3}, [%4];"
        : "=r"(r[0]), "=r"(r[1]), "=r"(r[2]), "=r"(r[3]) : "r"(addr));
}

__device__ __forceinline__ void mma_f16(float d[4], const uint32_t a[4], const uint32_t b[2]) {
    asm volatile(
        "mma.sync.aligned.m16n8k16.row.col.f32.f16.f16.f32 "
        "{%0,%1,%2,%3}, {%4,%5,%6,%7}, {%8,%9}, {%0,%1,%2,%3};"
        : "+f"(d[0]), "+f"(d[1]), "+f"(d[2]), "+f"(d[3])
        : "r"(a[0]), "r"(a[1]), "r"(a[2]), "r"(a[3]), "r"(b[0]), "r"(b[1]));
}

__device__ __forceinline__ uint32_t h2u(__half2 v) {
    union { __half2 h; uint32_t u; } c; c.h = v; return c.u;
}

// ---------------------------------------------------------------------------
// fp32 -> fp16 (hi [, lo]) split
// ---------------------------------------------------------------------------
template<int WRITE_LO>
__global__ void __launch_bounds__(256) split_f32h(
    const float* __restrict__ src, uint16_t* __restrict__ hi,
    uint16_t* __restrict__ lo, int n4)
{
    int i = blockIdx.x * 256 + threadIdx.x;
    if (i >= n4) return;
    float4 v = ((const float4*)src)[i];
    __half a0 = __float2half(v.x), a1 = __float2half(v.y);
    __half a2 = __float2half(v.z), a3 = __float2half(v.w);
    ((__half2*)hi)[2 * i]     = __halves2half2(a0, a1);
    ((__half2*)hi)[2 * i + 1] = __halves2half2(a2, a3);
    if (WRITE_LO) {
        ((__half2*)lo)[2 * i]     = __halves2half2(
            __float2half(v.x - __half2float(a0)), __float2half(v.y - __half2float(a1)));
        ((__half2*)lo)[2 * i + 1] = __halves2half2(
            __float2half(v.z - __half2float(a2)), __float2half(v.w - __half2float(a3)));
    }
}

// ---------------------------------------------------------------------------
// mma.sync fp16 2-term GEMM: C[M,N] = Ah[M,K] @ (Bh+Bl)[N,K]^T + bias
// CTA 128x128, 8 warps (2M x 4N), 3-stage cp.async ring.
// WOUT: 0 fp32 only, 1 fp16-hi only.
// ---------------------------------------------------------------------------
#define GEMM_SMEM (1024 + 3 * 32768)

template<int DO_GELU, int WOUT>
__global__ void __launch_bounds__(256, 2) gemm_mma(
    const uint16_t* __restrict__ Ahi,
    const uint16_t* __restrict__ Bhi, const uint16_t* __restrict__ Blo,
    const float* __restrict__ bias,
    float* __restrict__ Cf, uint16_t* __restrict__ Chi,
    int N, int K)
{
    extern __shared__ char smraw[];
    const uint32_t sb = (smem_u32(smraw) + 1023u) & ~1023u;
    const int tid = threadIdx.x;
    const int wid = tid >> 5, lane = tid & 31;
    const int wm = wid >> 2, wn = wid & 3;      // 2 x 4 warp grid
    const int m0 = blockIdx.y << 7, n0 = blockIdx.x << 7;
    const int KC = K >> 6;
    const int NC = 2 * KC;

    auto load_chunk = [&](int c, int s) {
        const int seg = c / KC;
        const int k0 = (c - seg * KC) << 6;
        const uint16_t* Bs = (seg == 1) ? Blo : Bhi;
        const uint32_t stA = sb + s * 32768;
        const uint32_t stB = stA + 16384;
        #pragma unroll
        for (int j = 0; j < 4; j++) {
            int i = tid + (j << 8);                 // 0..1023
            int r = i >> 3, cc = i & 7;
            uint32_t off = SWZ128((uint32_t)(r * 128 + cc * 16));
            CP16(stA + off, Ahi + (size_t)(m0 + r) * K + k0 + (cc << 3));
        }
        #pragma unroll
        for (int j = 0; j < 4; j++) {
            int i = tid + (j << 8);
            int r = i >> 3, cc = i & 7;
            uint32_t off = SWZ128((uint32_t)(r * 128 + cc * 16));
            CP16(stB + off, Bs + (size_t)(n0 + r) * K + k0 + (cc << 3));
        }
        CP_COMMIT();
    };

    load_chunk(0, 0);
    load_chunk(1, 1);

    float acc[4][4][4];
    #pragma unroll
    for (int mi = 0; mi < 4; mi++)
        #pragma unroll
        for (int nj = 0; nj < 4; nj++)
            #pragma unroll
            for (int q = 0; q < 4; q++) acc[mi][nj][q] = 0.f;

    const int a_row = wm * 64 + (lane & 15);
    const int a_kc8 = (lane >> 4) << 3;             // 0 or 8
    const int b_row = wn * 32 + (lane & 7) + ((lane & 16) ? 8 : 0);
    const int b_kc8 = (lane & 8);                   // 0 or 8

    for (int c = 0; c < NC; c++) {
        if (c < NC - 1) CP_WAIT1(); else CP_WAIT0();
        __syncthreads();        // single barrier: orders prev reads vs next writes too
        if (c + 2 < NC) load_chunk(c + 2, (c + 2) % 3);

        const uint32_t stA = sb + (c % 3) * 32768;
        const uint32_t stB = stA + 16384;
        #pragma unroll
        for (int kk = 0; kk < 4; kk++) {
            const int k0 = kk << 4;
            uint32_t a[4][4];
            #pragma unroll
            for (int mi = 0; mi < 4; mi++) {
                uint32_t off = (uint32_t)((a_row + mi * 16) * 128 + (k0 + a_kc8) * 2);
                ldsm4(a[mi], stA + SWZ128(off));
            }
            uint32_t b[4][2];
            #pragma unroll
            for (int pr = 0; pr < 2; pr++) {
                uint32_t r4[4];
                uint32_t off = (uint32_t)((b_row + pr * 16) * 128 + (k0 + b_kc8) * 2);
                ldsm4(r4, stB + SWZ128(off));
                b[pr * 2][0] = r4[0]; b[pr * 2][1] = r4[1];
                b[pr * 2 + 1][0] = r4[2]; b[pr * 2 + 1][1] = r4[3];
            }
            #pragma unroll
            for (int mi = 0; mi < 4; mi++)
                #pragma unroll
                for (int nj = 0; nj < 4; nj++)
                    mma_f16(acc[mi][nj], a[mi], b[nj]);
        }
    }

    const int r_base = m0 + wm * 64 + (lane >> 2);
    const int c_base = n0 + wn * 32 + 2 * (lane & 3);
    #pragma unroll
    for (int nj = 0; nj < 4; nj++) {
        const int col = c_base + nj * 8;
        const float b0 = bias[col], b1 = bias[col + 1];
        #pragma unroll
        for (int mi = 0; mi < 4; mi++) {
            #pragma unroll
            for (int h = 0; h < 2; h++) {
                const int row = r_base + mi * 16 + h * 8;
                float x0 = acc[mi][nj][2 * h]     + b0;
                float x1 = acc[mi][nj][2 * h + 1] + b1;
                if (DO_GELU) { x0 = gelu_exact(x0); x1 = gelu_exact(x1); }
                if (WOUT == 0) {
                    *(float2*)(Cf + (size_t)row * N + col) = make_float2(x0, x1);
                } else {
                    *(__half2*)((__half*)Chi + (size_t)row * N + col) =
                        __halves2half2(__float2half(x0), __float2half(x1));
                }
            }
        }
    }
}

// ---------------------------------------------------------------------------
// Flash attention, tensor-core fp16 2-term.
// One CTA per (b, h, 64-q tile); 4 warps. Q hi-only, K hi+lo, V hi+lo (transposed).
// QK^T: Qh*Kh + Qh*Kl.  PV: Ph*Vh + Ph*Vl.  fp32 accum + online softmax.
// SMEM: Qh|Kh|Kl|Vth|Vtl, 8KB each = 40KB.
// ---------------------------------------------------------------------------
#define ATT_SMEM 40960

__global__ void __launch_bounds__(128) attn_flash(
    const float* __restrict__ qkv, uint16_t* __restrict__ ctx_h16)
{
    __half* ctx_h = (__half*)ctx_h16;
    extern __shared__ char smraw[];
    const uint32_t sb = smem_u32(smraw);
    const uint32_t sQh = sb;
    const uint32_t sKh = sb + 8192, sKl = sb + 16384;
    const uint32_t sVh = sb + 24576, sVl = sb + 32768;

    const int tid = threadIdx.x;
    const int wid = tid >> 5, lane = tid & 31;
    const int qt = blockIdx.x, h = blockIdx.y, b = blockIdx.z;
    const size_t rowbase = (size_t)b * SEQ * 3 * WDIM;
    const int hoff = h * DH;

    // ---- Q tile (scaled), fp16 hi only ----
    for (int e = tid; e < 1024; e += 128) {
        int r = e >> 4, d4 = (e & 15) << 2;
        float4 v = *(const float4*)(qkv + rowbase + (size_t)(qt * 64 + r) * 3 * WDIM + hoff + d4);
        uint32_t o = SWZ128((uint32_t)(r * 128 + d4 * 2));
        *(__half2*)(smraw + o)     = __halves2half2(__float2half(v.x * 0.125f), __float2half(v.y * 0.125f));
        *(__half2*)(smraw + o + 4) = __halves2half2(__float2half(v.z * 0.125f), __float2half(v.w * 0.125f));
    }

    float m0r = -1e30f, m1r = -1e30f, l0r = 0.f, l1r = 0.f;
    float O[8][4];
    #pragma unroll
    for (int nb = 0; nb < 8; nb++)
        #pragma unroll
        for (int q = 0; q < 4; q++) O[nb][q] = 0.f;

    const int a_row = wid * 16 + (lane & 15);
    const int a_k8 = (lane >> 4) << 3;
    const int b_r  = (lane & 7) + ((lane & 16) ? 8 : 0);
    const int b_k8 = lane & 8;

    for (int kt = 0; kt < SEQ / 64; kt++) {
        __syncthreads();
        // ---- K (hi+lo) + V (hi+lo, transposed) ----
        for (int e = tid; e < 1024; e += 128) {
            int r = e >> 4, d4 = (e & 15) << 2;
            size_t gbase = rowbase + (size_t)(kt * 64 + r) * 3 * WDIM + hoff + d4;
            float4 kv = *(const float4*)(qkv + gbase + WDIM);
            __half k0 = __float2half(kv.x), k1 = __float2half(kv.y);
            __half k2 = __float2half(kv.z), k3 = __float2half(kv.w);
            uint32_t o = SWZ128((uint32_t)(r * 128 + d4 * 2));
            *(__half2*)(smraw + 8192 + o)      = __halves2half2(k0, k1);
            *(__half2*)(smraw + 8192 + o + 4)  = __halves2half2(k2, k3);
            *(__half2*)(smraw + 16384 + o)     = __halves2half2(
                __float2half(kv.x - __half2float(k0)), __float2half(kv.y - __half2float(k1)));
            *(__half2*)(smraw + 16384 + o + 4) = __halves2half2(
                __float2half(kv.z - __half2float(k2)), __float2half(kv.w - __half2float(k3)));
            float4 vv = *(const float4*)(qkv + gbase + 2 * WDIM);
            const float* vp = &vv.x;
            #pragma unroll
            for (int i = 0; i < 4; i++) {
                float x = vp[i];
                __half hh = __float2half(x);
                __half ll = __float2half(x - __half2float(hh));
                uint32_t ov = SWZ128((uint32_t)((d4 + i) * 128 + r * 2));
                *(__half*)(smraw + 24576 + ov) = hh;
                *(__half*)(smraw + 32768 + ov) = ll;
            }
        }
        __syncthreads();

        // ---- S = QK^T (2-term) ----
        float S[8][4];
        #pragma unroll
        for (int nb = 0; nb < 8; nb++)
            #pragma unroll
            for (int q = 0; q < 4; q++) S[nb][q] = 0.f;

        #pragma unroll
        for (int kk = 0; kk < 4; kk++) {
            uint32_t aoff = SWZ128((uint32_t)(a_row * 128 + (kk * 16 + a_k8) * 2));
            uint32_t aH[4];
            ldsm4(aH, sQh + aoff);
            uint32_t bh[8][2], bl[8][2];
            #pragma unroll
            for (int pr = 0; pr < 4; pr++) {
                uint32_t boff = SWZ128((uint32_t)((pr * 16 + b_r) * 128 + (kk * 16 + b_k8) * 2));
                uint32_t r4[4];
                ldsm4(r4, sKh + boff);
                bh[pr * 2][0] = r4[0]; bh[pr * 2][1] = r4[1];
                bh[pr * 2 + 1][0] = r4[2]; bh[pr * 2 + 1][1] = r4[3];
                ldsm4(r4, sKl + boff);
                bl[pr * 2][0] = r4[0]; bl[pr * 2][1] = r4[1];
                bl[pr * 2 + 1][0] = r4[2]; bl[pr * 2 + 1][1] = r4[3];
            }
            #pragma unroll
            for (int nb = 0; nb < 8; nb++) {
                mma_f16(S[nb], aH, bh[nb]);
                mma_f16(S[nb], aH, bl[nb]);
            }
        }

        // ---- online softmax ----
        float mx0 = -1e30f, mx1 = -1e30f;
        #pragma unroll
        for (int nb = 0; nb < 8; nb++) {
            mx0 = fmaxf(mx0, fmaxf(S[nb][0], S[nb][1]));
            mx1 = fmaxf(mx1, fmaxf(S[nb][2], S[nb][3]));
        }
        mx0 = fmaxf(mx0, __shfl_xor_sync(0xffffffffu, mx0, 1));
        mx0 = fmaxf(mx0, __shfl_xor_sync(0xffffffffu, mx0, 2));
        mx1 = fmaxf(mx1, __shfl_xor_sync(0xffffffffu, mx1, 1));
        mx1 = fmaxf(mx1, __shfl_xor_sync(0xffffffffu, mx1, 2));
        float nm0 = fmaxf(m0r, mx0), nm1 = fmaxf(m1r, mx1);
        float al0 = __expf(m0r - nm0), al1 = __expf(m1r - nm1);
        m0r = nm0; m1r = nm1;
        float sum0 = 0.f, sum1 = 0.f;
        #pragma unroll
        for (int nb = 0; nb < 8; nb++) {
            S[nb][0] = __expf(S[nb][0] - nm0); sum0 += S[nb][0];
            S[nb][1] = __expf(S[nb][1] - nm0); sum0 += S[nb][1];
            S[nb][2] = __expf(S[nb][2] - nm1); sum1 += S[nb][2];
            S[nb][3] = __expf(S[nb][3] - nm1); sum1 += S[nb][3];
        }
        sum0 += __shfl_xor_sync(0xffffffffu, sum0, 1);
        sum0 += __shfl_xor_sync(0xffffffffu, sum0, 2);
        sum1 += __shfl_xor_sync(0xffffffffu, sum1, 1);
        sum1 += __shfl_xor_sync(0xffffffffu, sum1, 2);
        l0r = l0r * al0 + sum0;
        l1r = l1r * al1 + sum1;
        #pragma unroll
        for (int nb = 0; nb < 8; nb++) {
            O[nb][0] *= al0; O[nb][1] *= al0;
            O[nb][2] *= al1; O[nb][3] *= al1;
        }

        // ---- O += P*V (2-term), P hi-only packed in-register ----
        #pragma unroll
        for (int kk = 0; kk < 4; kk++) {
            uint32_t ph[4];
            ph[0] = h2u(__halves2half2(__float2half(S[2*kk][0]),   __float2half(S[2*kk][1])));
            ph[1] = h2u(__halves2half2(__float2half(S[2*kk][2]),   __float2half(S[2*kk][3])));
            ph[2] = h2u(__halves2half2(__float2half(S[2*kk+1][0]), __float2half(S[2*kk+1][1])));
            ph[3] = h2u(__halves2half2(__float2half(S[2*kk+1][2]), __float2half(S[2*kk+1][3])));
            uint32_t bh[8][2], bl[8][2];
            #pragma unroll
            for (int pr = 0; pr < 4; pr++) {
                uint32_t boff = SWZ128((uint32_t)((pr * 16 + b_r) * 128 + (kk * 16 + b_k8) * 2));
                uint32_t r4[4];
                ldsm4(r4, sVh + boff);
                bh[pr * 2][0] = r4[0]; bh[pr * 2][1] = r4[1];
                bh[pr * 2 + 1][0] = r4[2]; bh[pr * 2 + 1][1] = r4[3];
                ldsm4(r4, sVl + boff);
                bl[pr * 2][0] = r4[0]; bl[pr * 2][1] = r4[1];
                bl[pr * 2 + 1][0] = r4[2]; bl[pr * 2 + 1][1] = r4[3];
            }
            #pragma unroll
            for (int nb = 0; nb < 8; nb++) {
                mma_f16(O[nb], ph, bh[nb]);
                mma_f16(O[nb], ph, bl[nb]);
            }
        }
    }

    // ---- epilogue: normalize, write fp16 hi ctx ----
    const float i0 = 1.f / l0r, i1 = 1.f / l1r;
    const int r0 = b * SEQ + qt * 64 + wid * 16 + (lane >> 2);
    const int c0 = hoff + 2 * (lane & 3);
    #pragma unroll
    for (int nb = 0; nb < 8; nb++) {
        const int col = c0 + nb * 8;
        *(__half2*)(ctx_h + (size_t)r0 * WDIM + col) =
            __halves2half2(__float2half(O[nb][0] * i0), __float2half(O[nb][1] * i0));
        *(__half2*)(ctx_h + (size_t)(r0 + 8) * WDIM + col) =
            __halves2half2(__float2half(O[nb][2] * i1), __float2half(O[nb][3] * i1));
    }
}

// ---------------------------------------------------------------------------
// Residual add + LayerNorm. SPLIT: 0 none, 1 fp16-hi out.
// ---------------------------------------------------------------------------
template<int SPLIT>
__global__ void __launch_bounds__(256) ln_residual(
    const float* __restrict__ x, const float* __restrict__ r,
    const float* __restrict__ gamma, const float* __restrict__ beta,
    float* __restrict__ out, uint16_t* __restrict__ oh)
{
    __shared__ float red[2][8];
    __shared__ float stats[2];
    const int row = blockIdx.x, tid = threadIdx.x;
    const size_t base = (size_t)row * WDIM;
    float v[4];
    float s = 0.f, sq = 0.f;
    #pragma unroll
    for (int c = 0; c < 4; c++) {
        int w = tid + c * 256;
        float a = x[base + w] + r[base + w];
        v[c] = a; s += a; sq += a * a;
    }
    #pragma unroll
    for (int off = 16; off; off >>= 1) {
        s  += __shfl_xor_sync(0xffffffffu, s, off);
        sq += __shfl_xor_sync(0xffffffffu, sq, off);
    }
    int lane = tid & 31, wid = tid >> 5;
    if (lane == 0) { red[0][wid] = s; red[1][wid] = sq; }
    __syncthreads();
    if (tid == 0) {
        float ts = 0.f, tq = 0.f;
        #pragma unroll
        for (int w = 0; w < 8; w++) { ts += red[0][w]; tq += red[1][w]; }
        float mean = ts * (1.f / WDIM);
        float var  = tq * (1.f / WDIM) - mean * mean;
        stats[0] = mean;
        stats[1] = rsqrtf(var + 1e-5f);
    }
    __syncthreads();
    float mean = stats[0], rstd = stats[1];
    #pragma unroll
    for (int c = 0; c < 4; c++) {
        int w = tid + c * 256;
        float o = (v[c] - mean) * rstd * gamma[w] + beta[w];
        out[base + w] = o;
        if (SPLIT) ((__half*)oh)[base + w] = __float2half(o);
    }
}

// ---------------------------------------------------------------------------
// Topic kernel (unchanged)
// ---------------------------------------------------------------------------
__global__ void __launch_bounds__(256) topic_kernel(
    const float* __restrict__ hidden, const int* __restrict__ in_ids,
    const int* __restrict__ res_ids, const float* __restrict__ tw,
    const float* __restrict__ tb, const float* __restrict__ tt,
    float* __restrict__ ue)
{
    __shared__ float mp[WDIM];
    __shared__ float logits[64];
    __shared__ float probs[64];
    __shared__ int sid[SEQ];
    const int tid = threadIdx.x;
    const int g = blockIdx.x, b = blockIdx.y;

    for (int s = tid; s < SEQ; s += 256) {
        int id;
        if (g < 6) id = (s < S_IN) ? in_ids[b * S_IN + s] : 0;
        else       id = (s >= S_IN) ? res_ids[b * 129 + (s - S_IN + 1)] : 0;
        sid[s] = id;
    }
    __syncthreads();

    const int gid = (g < 6) ? (g + 1) : 1;
    float acc[4] = {0.f, 0.f, 0.f, 0.f};
    for (int s = 0; s < SEQ; s++) {
        if (sid[s] == gid) {
            const float* hr = hidden + (size_t)(b * SEQ + s) * WDIM;
            #pragma unroll
            for (int c = 0; c < 4; c++)
                acc[c] = fmaxf(acc[c], hr[tid + c * 256]);
        }
    }
    #pragma unroll
    for (int c = 0; c < 4; c++) mp[tid + c * 256] = acc[c];
    __syncthreads();

    int lane = tid & 31, wid = tid >> 5;
    for (int t = wid; t < NTOP; t += 8) {
        const float* wrow = tw + (size_t)t * WDIM;
        float d = 0.f;
        for (int w = lane; w < WDIM; w += 32) d += mp[w] * wrow[w];
        #pragma unroll
        for (int off = 16; off; off >>= 1)
            d += __shfl_xor_sync(0xffffffffu, d, off);
        if (lane == 0) logits[t] = d + tb[t];
    }
    __syncthreads();

    if (tid < 32) {
        float mval = -1e30f;
        for (int t = tid; t < NTOP; t += 32) mval = fmaxf(mval, logits[t]);
        #pragma unroll
        for (int off = 16; off; off >>= 1)
            mval = fmaxf(mval, __shfl_xor_sync(0xffffffffu, mval, off));
        float ssum = 0.f;
        for (int t = tid; t < NTOP; t += 32) {
            float p = __expf(logits[t] - mval);
            probs[t] = p; ssum += p;
        }
        #pragma unroll
        for (int off = 16; off; off >>= 1)
            ssum += __shfl_xor_sync(0xffffffffu, ssum, off);
        float inv = 1.f / ssum;
        for (int t = tid; t < NTOP; t += 32) probs[t] *= inv;
    }
    __syncthreads();

    float uacc[4] = {0.f, 0.f, 0.f, 0.f};
    for (int t = 0; t < NTOP; t++) {
        float p = probs[t];
        const float* trow = tt + (size_t)t * WDIM;
        #pragma unroll
        for (int c = 0; c < 4; c++) uacc[c] += p * trow[tid + c * 256];
    }
    float* urow = ue + (size_t)(b * NGRP + g) * WDIM;
    #pragma unroll
    for (int c = 0; c < 4; c++) urow[tid + c * 256] = uacc[c];
}

// ---------------------------------------------------------------------------
// Final scatter-add (unchanged)
// ---------------------------------------------------------------------------
__global__ void __launch_bounds__(256) final_add(
    const float* __restrict__ inp, const int* __restrict__ in_ids,
    const int* __restrict__ res_ids, const float* __restrict__ ue,
    float* __restrict__ out)
{
    const int row = blockIdx.x, tid = threadIdx.x;
    const int b = row >> 9, s = row & 511;
    int g = 0; float mult = 0.f;
    if (s < S_IN) {
        int id = in_ids[b * S_IN + s];
        if (id > 0)      { g = id - 1;  mult = 1.f; }
        else if (id < 0) { g = -id - 1; mult = 2.f; }
    } else {
        int id = res_ids[b * 129 + (s - S_IN + 1)];
        g = 6;
        if (id > 0)      mult = 1.f;
        else if (id < 0) mult = 2.f;
    }
    const size_t base = (size_t)row * WDIM;
    const float* urow = ue + (size_t)(b * NGRP + g) * WDIM;
    #pragma unroll
    for (int c = 0; c < 4; c++) {
        int w = tid + c * 256;
        out[base + w] = inp[base + w] + mult * urow[w];
    }
}

// ---------------------------------------------------------------------------
// Launch
// ---------------------------------------------------------------------------
extern "C" void kernel_launch(void* const* d_in, const int* in_sizes, int n_in,
                              void* d_out, int out_size)
{
    const float* inp     = (const float*)d_in[0];
    const int*   in_ids  = (const int*)  d_in[1];
    const int*   res_ids = (const int*)  d_in[2];
    const float* Wqkv    = (const float*)d_in[3];
    const float* bqkv    = (const float*)d_in[4];
    const float* Wo      = (const float*)d_in[5];
    const float* bo      = (const float*)d_in[6];
    const float* ln1g    = (const float*)d_in[7];
    const float* ln1b    = (const float*)d_in[8];
    const float* W1      = (const float*)d_in[9];
    const float* b1      = (const float*)d_in[10];
    const float* W2      = (const float*)d_in[11];
    const float* b2      = (const float*)d_in[12];
    const float* ln2g    = (const float*)d_in[13];
    const float* ln2b    = (const float*)d_in[14];
    const float* tw      = (const float*)d_in[15];
    const float* tb      = (const float*)d_in[16];
    const float* tt      = (const float*)d_in[17];
    float* out = (float*)d_out;

    float *qkv, *tmp, *y, *hidden, *ue;
    cudaGetSymbolAddress((void**)&qkv,    g_qkv);
    cudaGetSymbolAddress((void**)&tmp,    g_tmp);
    cudaGetSymbolAddress((void**)&y,      g_y);
    cudaGetSymbolAddress((void**)&hidden, g_hidden);
    cudaGetSymbolAddress((void**)&ue,     g_ue);

    uint16_t *inp_h, *ctx_h, *yh, *ffh;
    uint16_t *wqkv_h, *wqkv_l, *wo_h, *wo_l, *w1_h, *w1_l, *w2_h, *w2_l;
    cudaGetSymbolAddress((void**)&inp_h,  g_inp_h);
    cudaGetSymbolAddress((void**)&ctx_h,  g_ctx_h);
    cudaGetSymbolAddress((void**)&yh,     g_yh);
    cudaGetSymbolAddress((void**)&ffh,    g_ffh);
    cudaGetSymbolAddress((void**)&wqkv_h, g_wqkv_h);
    cudaGetSymbolAddress((void**)&wqkv_l, g_wqkv_l);
    cudaGetSymbolAddress((void**)&wo_h,   g_wo_h);
    cudaGetSymbolAddress((void**)&wo_l,   g_wo_l);
    cudaGetSymbolAddress((void**)&w1_h,   g_w1_h);
    cudaGetSymbolAddress((void**)&w1_l,   g_w1_l);
    cudaGetSymbolAddress((void**)&w2_h,   g_w2_h);
    cudaGetSymbolAddress((void**)&w2_l,   g_w2_l);

    cudaFuncSetAttribute(attn_flash,
                         cudaFuncAttributeMaxDynamicSharedMemorySize, ATT_SMEM);
    cudaFuncSetAttribute(gemm_mma<0,0>,
                         cudaFuncAttributeMaxDynamicSharedMemorySize, GEMM_SMEM);
    cudaFuncSetAttribute(gemm_mma<1,1>,
                         cudaFuncAttributeMaxDynamicSharedMemorySize, GEMM_SMEM);

    // 0) fp32 -> fp16 splits: activations hi-only, weights hi+lo
    auto split_hi = [&](const float* s, uint16_t* h, size_t n) {
        int n4 = (int)(n / 4);
        split_f32h<0><<<(n4 + 255) / 256, 256>>>(s, h, nullptr, n4);
    };
    auto split_hl = [&](const float* s, uint16_t* h, uint16_t* l, size_t n) {
        int n4 = (int)(n / 4);
        split_f32h<1><<<(n4 + 255) / 256, 256>>>(s, h, l, n4);
    };
    split_hi(inp,  inp_h,  (size_t)MTOT * WDIM);
    split_hl(Wqkv, wqkv_h, wqkv_l, (size_t)3 * WDIM * WDIM);
    split_hl(Wo,   wo_h,   wo_l,   (size_t)WDIM * WDIM);
    split_hl(W1,   w1_h,   w1_l,   (size_t)DFFDIM * WDIM);
    split_hl(W2,   w2_h,   w2_l,   (size_t)WDIM * DFFDIM);

    // 1) QKV projection (fp16 2-term): qkv = inp @ Wqkv^T + bqkv
    gemm_mma<0,0><<<dim3(3 * WDIM / 128, MTOT / 128), 256, GEMM_SMEM>>>(
        inp_h, wqkv_h, wqkv_l, bqkv, qkv, nullptr, 3 * WDIM, WDIM);
    // 2) Attention (fp16 2-term tensor) -> ctx hi
    attn_flash<<<dim3(SEQ / 64, HEADS, BATCH), 128, ATT_SMEM>>>(qkv, ctx_h);
    // 3) O projection (fp16 2-term): tmp = ctx @ Wo^T + bo
    gemm_mma<0,0><<<dim3(WDIM / 128, MTOT / 128), 256, GEMM_SMEM>>>(
        ctx_h, wo_h, wo_l, bo, tmp, nullptr, WDIM, WDIM);
    // 4) LN1(inp + tmp) -> y (fp32) + yh (fp16)
    ln_residual<1><<<MTOT, 256>>>(inp, tmp, ln1g, ln1b, y, yh);
    // 5) FF1 + GELU (fp16 2-term): ffh = gelu(y @ W1^T + b1)
    gemm_mma<1,1><<<dim3(DFFDIM / 128, MTOT / 128), 256, GEMM_SMEM>>>(
        yh, w1_h, w1_l, b1, nullptr, ffh, DFFDIM, WDIM);
    // 6) FF2 (fp16 2-term): tmp = ff @ W2^T + b2
    gemm_mma<0,0><<<dim3(WDIM / 128, MTOT / 128), 256, GEMM_SMEM>>>(
        ffh, w2_h, w2_l, b2, tmp, nullptr, WDIM, DFFDIM);
    // 7) LN2(y + tmp) -> hidden
    ln_residual<0><<<MTOT, 256>>>(y, tmp, ln2g, ln2b, hidden, nullptr);
    // 8) Topic embeddings
    topic_kernel<<<dim3(NGRP, BATCH), 256>>>(hidden, in_ids, res_ids, tw, tb, tt, ue);
    // 9) Final scatter-add
    final_add<<<MTOT, 256>>>(inp, in_ids, res_ids, ue, out);
}

// round 17
// speedup vs baseline: 5.3510x; 1.1056x over previous
#include <cuda_runtime.h>
#include <cuda_bf16.h>
#include <cuda_fp16.h>
#include <math.h>
#include <cstdint>

// ---------------------------------------------------------------------------
// Problem constants
// ---------------------------------------------------------------------------
#define BATCH   16
#define SEQ     512
#define S_IN    384
#define WDIM    1024
#define HEADS   16
#define DH      64
#define DFFDIM  4096
#define NTOP    50
#define NGRP    7
#define MTOT    (BATCH*SEQ)          // 8192 rows

// ---------------------------------------------------------------------------
// Scratch (static device globals). All 16-bit buffers hold fp16.
// ---------------------------------------------------------------------------
__device__ __align__(256) float g_tmp[(size_t)MTOT * WDIM];
__device__ __align__(256) float g_y[(size_t)MTOT * WDIM];
__device__ __align__(256) float g_hidden[(size_t)MTOT * WDIM];
__device__ __align__(256) float g_ue[(size_t)BATCH * NGRP * WDIM];

__device__ __align__(256) uint16_t g_qkv_h[(size_t)MTOT * 3 * WDIM];
__device__ __align__(256) uint16_t g_qkv_l[(size_t)MTOT * 3 * WDIM];
__device__ __align__(256) uint16_t g_inp_h[(size_t)MTOT * WDIM];
__device__ __align__(256) uint16_t g_ctx_h[(size_t)MTOT * WDIM];
__device__ __align__(256) uint16_t g_yh[(size_t)MTOT * WDIM];
__device__ __align__(256) uint16_t g_ffh[(size_t)MTOT * DFFDIM];
__device__ __align__(256) uint16_t g_wqkv_h[(size_t)3 * WDIM * WDIM];
__device__ __align__(256) uint16_t g_wqkv_l[(size_t)3 * WDIM * WDIM];
__device__ __align__(256) uint16_t g_wo_h[(size_t)WDIM * WDIM];
__device__ __align__(256) uint16_t g_wo_l[(size_t)WDIM * WDIM];
__device__ __align__(256) uint16_t g_w1_h[(size_t)DFFDIM * WDIM];
__device__ __align__(256) uint16_t g_w1_l[(size_t)DFFDIM * WDIM];
__device__ __align__(256) uint16_t g_w2_h[(size_t)WDIM * DFFDIM];
__device__ __align__(256) uint16_t g_w2_l[(size_t)WDIM * DFFDIM];

__device__ __forceinline__ float gelu_exact(float x) {
    return 0.5f * x * (1.0f + erff(x * 0.70710678118654752f));
}

// ---------------------------------------------------------------------------
// PTX helpers
// ---------------------------------------------------------------------------
__device__ __forceinline__ uint32_t smem_u32(const void* p) {
    uint32_t a;
    asm("{ .reg .u64 t; cvta.to.shared.u64 t, %1; cvt.u32.u64 %0, t; }"
        : "=r"(a) : "l"(p));
    return a;
}
#define SWZ128(off) ((off) ^ (((off) >> 3) & 0x70))

#define CP16(dst, src) \
    asm volatile("cp.async.cg.shared.global [%0], [%1], 16;" \
        :: "r"(dst), "l"(__cvta_generic_to_global(src)) : "memory")
#define CP_COMMIT() asm volatile("cp.async.commit_group;" ::: "memory")
#define CP_WAIT1() asm volatile("cp.async.wait_group 1;" ::: "memory")
#define CP_WAIT0() asm volatile("cp.async.wait_group 0;" ::: "memory")

__device__ __forceinline__ void ldsm4(uint32_t r[4], uint32_t addr) {
    asm volatile("ldmatrix.sync.aligned.m8n8.x4.shared.b16 {%0,%1,%2,%3}, [%4];"
        : "=r"(r[0]), "=r"(r[1]), "=r"(r[2]), "=r"(r[3]) : "r"(addr));
}

__device__ __forceinline__ void mma_f16(float d[4], const uint32_t a[4], const uint32_t b[2]) {
    asm volatile(
        "mma.sync.aligned.m16n8k16.row.col.f32.f16.f16.f32 "
        "{%0,%1,%2,%3}, {%4,%5,%6,%7}, {%8,%9}, {%0,%1,%2,%3};"
        : "+f"(d[0]), "+f"(d[1]), "+f"(d[2]), "+f"(d[3])
        : "r"(a[0]), "r"(a[1]), "r"(a[2]), "r"(a[3]), "r"(b[0]), "r"(b[1]));
}

__device__ __forceinline__ uint32_t h2u(__half2 v) {
    union { __half2 h; uint32_t u; } c; c.h = v; return c.u;
}

// ---------------------------------------------------------------------------
// fp32 -> fp16 (hi [, lo]) split
// ---------------------------------------------------------------------------
template<int WRITE_LO>
__global__ void __launch_bounds__(256) split_f32h(
    const float* __restrict__ src, uint16_t* __restrict__ hi,
    uint16_t* __restrict__ lo, int n4)
{
    int i = blockIdx.x * 256 + threadIdx.x;
    if (i >= n4) return;
    float4 v = ((const float4*)src)[i];
    __half a0 = __float2half(v.x), a1 = __float2half(v.y);
    __half a2 = __float2half(v.z), a3 = __float2half(v.w);
    ((__half2*)hi)[2 * i]     = __halves2half2(a0, a1);
    ((__half2*)hi)[2 * i + 1] = __halves2half2(a2, a3);
    if (WRITE_LO) {
        ((__half2*)lo)[2 * i]     = __halves2half2(
            __float2half(v.x - __half2float(a0)), __float2half(v.y - __half2float(a1)));
        ((__half2*)lo)[2 * i + 1] = __halves2half2(
            __float2half(v.z - __half2float(a2)), __float2half(v.w - __half2float(a3)));
    }
}

// ---------------------------------------------------------------------------
// mma.sync fp16 2-term GEMM: C[M,N] = Ah[M,K] @ (Bh+Bl)[N,K]^T + bias
// CTA 128x128, 8 warps (2M x 4N). Combined stage {A | Bh | Bl} (48KB),
// 2-stage cp.async ring: A loaded ONCE per K-chunk, both B segments MMA'd.
// WOUT: 0 fp32, 1 fp16-hi, 2 fp16 hi+lo.
// ---------------------------------------------------------------------------
#define GEMM_SMEM (1024 + 2 * 49152)

template<int DO_GELU, int WOUT>
__global__ void __launch_bounds__(256, 2) gemm_mma(
    const uint16_t* __restrict__ Ahi,
    const uint16_t* __restrict__ Bhi, const uint16_t* __restrict__ Blo,
    const float* __restrict__ bias,
    float* __restrict__ Cf, uint16_t* __restrict__ Chi, uint16_t* __restrict__ Clo,
    int N, int K)
{
    extern __shared__ char smraw[];
    const uint32_t sb = (smem_u32(smraw) + 1023u) & ~1023u;
    const int tid = threadIdx.x;
    const int wid = tid >> 5, lane = tid & 31;
    const int wm = wid >> 2, wn = wid & 3;      // 2 x 4 warp grid
    const int m0 = blockIdx.y << 7, n0 = blockIdx.x << 7;
    const int KC = K >> 6;

    auto load_chunk = [&](int c, int s) {
        const int k0 = c << 6;
        const uint32_t st = sb + s * 49152;
        #pragma unroll
        for (int j = 0; j < 4; j++) {
            int i = tid + (j << 8);                 // 0..1023
            int r = i >> 3, cc = i & 7;
            uint32_t off = SWZ128((uint32_t)(r * 128 + cc * 16));
            CP16(st + off, Ahi + (size_t)(m0 + r) * K + k0 + (cc << 3));
        }
        #pragma unroll
        for (int j = 0; j < 4; j++) {
            int i = tid + (j << 8);
            int r = i >> 3, cc = i & 7;
            uint32_t off = SWZ128((uint32_t)(r * 128 + cc * 16));
            CP16(st + 16384 + off, Bhi + (size_t)(n0 + r) * K + k0 + (cc << 3));
        }
        #pragma unroll
        for (int j = 0; j < 4; j++) {
            int i = tid + (j << 8);
            int r = i >> 3, cc = i & 7;
            uint32_t off = SWZ128((uint32_t)(r * 128 + cc * 16));
            CP16(st + 32768 + off, Blo + (size_t)(n0 + r) * K + k0 + (cc << 3));
        }
        CP_COMMIT();
    };

    load_chunk(0, 0);
    load_chunk(1, 1);

    float acc[4][4][4];
    #pragma unroll
    for (int mi = 0; mi < 4; mi++)
        #pragma unroll
        for (int nj = 0; nj < 4; nj++)
            #pragma unroll
            for (int q = 0; q < 4; q++) acc[mi][nj][q] = 0.f;

    const int a_row = wm * 64 + (lane & 15);
    const int a_kc8 = (lane >> 4) << 3;             // 0 or 8
    const int b_row = wn * 32 + (lane & 7) + ((lane & 16) ? 8 : 0);
    const int b_kc8 = (lane & 8);                   // 0 or 8

    for (int c = 0; c < KC; c++) {
        if (c < KC - 1) CP_WAIT1(); else CP_WAIT0();
        __syncthreads();

        const uint32_t st = sb + (c & 1) * 49152;
        #pragma unroll
        for (int kk = 0; kk < 4; kk++) {
            const int k0 = kk << 4;
            uint32_t a[4][4];
            #pragma unroll
            for (int mi = 0; mi < 4; mi++) {
                uint32_t off = (uint32_t)((a_row + mi * 16) * 128 + (k0 + a_kc8) * 2);
                ldsm4(a[mi], st + SWZ128(off));
            }
            uint32_t bh[4][2], bl[4][2];
            #pragma unroll
            for (int pr = 0; pr < 2; pr++) {
                uint32_t off = SWZ128((uint32_t)((b_row + pr * 16) * 128 + (k0 + b_kc8) * 2));
                uint32_t r4[4];
                ldsm4(r4, st + 16384 + off);
                bh[pr * 2][0] = r4[0]; bh[pr * 2][1] = r4[1];
                bh[pr * 2 + 1][0] = r4[2]; bh[pr * 2 + 1][1] = r4[3];
                ldsm4(r4, st + 32768 + off);
                bl[pr * 2][0] = r4[0]; bl[pr * 2][1] = r4[1];
                bl[pr * 2 + 1][0] = r4[2]; bl[pr * 2 + 1][1] = r4[3];
            }
            #pragma unroll
            for (int mi = 0; mi < 4; mi++)
                #pragma unroll
                for (int nj = 0; nj < 4; nj++) {
                    mma_f16(acc[mi][nj], a[mi], bh[nj]);
                    mma_f16(acc[mi][nj], a[mi], bl[nj]);
                }
        }
        __syncthreads();
        if (c + 2 < KC) load_chunk(c + 2, c & 1);
    }

    const int r_base = m0 + wm * 64 + (lane >> 2);
    const int c_base = n0 + wn * 32 + 2 * (lane & 3);
    #pragma unroll
    for (int nj = 0; nj < 4; nj++) {
        const int col = c_base + nj * 8;
        const float b0 = bias[col], b1 = bias[col + 1];
        #pragma unroll
        for (int mi = 0; mi < 4; mi++) {
            #pragma unroll
            for (int h = 0; h < 2; h++) {
                const int row = r_base + mi * 16 + h * 8;
                float x0 = acc[mi][nj][2 * h]     + b0;
                float x1 = acc[mi][nj][2 * h + 1] + b1;
                if (DO_GELU) { x0 = gelu_exact(x0); x1 = gelu_exact(x1); }
                if (WOUT == 0) {
                    *(float2*)(Cf + (size_t)row * N + col) = make_float2(x0, x1);
                } else {
                    __half h0c = __float2half(x0), h1c = __float2half(x1);
                    *(__half2*)((__half*)Chi + (size_t)row * N + col) = __halves2half2(h0c, h1c);
                    if (WOUT == 2) {
                        *(__half2*)((__half*)Clo + (size_t)row * N + col) = __halves2half2(
                            __float2half(x0 - __half2float(h0c)),
                            __float2half(x1 - __half2float(h1c)));
                    }
                }
            }
        }
    }
}

// ---------------------------------------------------------------------------
// Flash attention, tensor-core fp16 2-term, fp16 inputs (hi+lo qkv).
// One CTA per (b, h, 64-q tile); 4 warps. Q hi-only (unscaled; 1/8 applied
// to S in fp32), K hi+lo via cp.async, V hi+lo transposed via ldg+sts.
// SMEM: Qh|Kh|Kl|Vth|Vtl, 8KB each = 40KB.
// ---------------------------------------------------------------------------
#define ATT_SMEM 40960

__global__ void __launch_bounds__(128) attn_flash(
    const uint16_t* __restrict__ qkvh, const uint16_t* __restrict__ qkvl,
    uint16_t* __restrict__ ctx_h16)
{
    __half* ctx_h = (__half*)ctx_h16;
    extern __shared__ char smraw[];
    const uint32_t sb = smem_u32(smraw);
    const uint32_t sQh = sb;
    const uint32_t sKh = sb + 8192, sKl = sb + 16384;
    const uint32_t sVh = sb + 24576, sVl = sb + 32768;

    const int tid = threadIdx.x;
    const int wid = tid >> 5, lane = tid & 31;
    const int qt = blockIdx.x, h = blockIdx.y, b = blockIdx.z;
    const int hoff = h * DH;

    // ---- Q tile: cp.async fp16 hi straight into swizzled smem ----
    #pragma unroll
    for (int j = 0; j < 4; j++) {
        int i = tid + (j << 7);                 // 0..511
        int r = i >> 3, cc = i & 7;
        CP16(sQh + SWZ128((uint32_t)(r * 128 + cc * 16)),
             qkvh + (size_t)(b * SEQ + qt * 64 + r) * 3 * WDIM + hoff + (cc << 3));
    }
    CP_COMMIT();

    float m0r = -1e30f, m1r = -1e30f, l0r = 0.f, l1r = 0.f;
    float O[8][4];
    #pragma unroll
    for (int nb = 0; nb < 8; nb++)
        #pragma unroll
        for (int q = 0; q < 4; q++) O[nb][q] = 0.f;

    const int a_row = wid * 16 + (lane & 15);
    const int a_k8 = (lane >> 4) << 3;
    const int b_r  = (lane & 7) + ((lane & 16) ? 8 : 0);
    const int b_k8 = lane & 8;

    for (int kt = 0; kt < SEQ / 64; kt++) {
        __syncthreads();    // prior compute done before overwriting K/V smem
        // ---- K hi+lo via cp.async ----
        #pragma unroll
        for (int j = 0; j < 4; j++) {
            int i = tid + (j << 7);
            int r = i >> 3, cc = i & 7;
            size_t gi = (size_t)(b * SEQ + kt * 64 + r) * 3 * WDIM + WDIM + hoff + (cc << 3);
            uint32_t off = SWZ128((uint32_t)(r * 128 + cc * 16));
            CP16(sKh + off, qkvh + gi);
            CP16(sKl + off, qkvl + gi);
        }
        // ---- V hi+lo: ldg fp16 + transposed scalar sts ----
        #pragma unroll
        for (int j = 0; j < 4; j++) {
            int i = tid + (j << 7);
            int r = i >> 3, d8 = (i & 7) << 3;
            size_t gi = (size_t)(b * SEQ + kt * 64 + r) * 3 * WDIM + 2 * WDIM + hoff + d8;
            uint4 vh = *(const uint4*)(qkvh + gi);
            uint4 vl = *(const uint4*)(qkvl + gi);
            const __half* ph = (const __half*)&vh;
            const __half* pl = (const __half*)&vl;
            #pragma unroll
            for (int q = 0; q < 8; q++) {
                uint32_t ov = SWZ128((uint32_t)((d8 + q) * 128 + r * 2));
                *(__half*)(smraw + 24576 + ov) = ph[q];
                *(__half*)(smraw + 32768 + ov) = pl[q];
            }
        }
        CP_COMMIT();
        CP_WAIT0();
        __syncthreads();

        // ---- S = QK^T (2-term), then scale by 1/8 in fp32 ----
        float S[8][4];
        #pragma unroll
        for (int nb = 0; nb < 8; nb++)
            #pragma unroll
            for (int q = 0; q < 4; q++) S[nb][q] = 0.f;

        #pragma unroll
        for (int kk = 0; kk < 4; kk++) {
            uint32_t aoff = SWZ128((uint32_t)(a_row * 128 + (kk * 16 + a_k8) * 2));
            uint32_t aH[4];
            ldsm4(aH, sQh + aoff);
            uint32_t bh[8][2], bl[8][2];
            #pragma unroll
            for (int pr = 0; pr < 4; pr++) {
                uint32_t boff = SWZ128((uint32_t)((pr * 16 + b_r) * 128 + (kk * 16 + b_k8) * 2));
                uint32_t r4[4];
                ldsm4(r4, sKh + boff);
                bh[pr * 2][0] = r4[0]; bh[pr * 2][1] = r4[1];
                bh[pr * 2 + 1][0] = r4[2]; bh[pr * 2 + 1][1] = r4[3];
                ldsm4(r4, sKl + boff);
                bl[pr * 2][0] = r4[0]; bl[pr * 2][1] = r4[1];
                bl[pr * 2 + 1][0] = r4[2]; bl[pr * 2 + 1][1] = r4[3];
            }
            #pragma unroll
            for (int nb = 0; nb < 8; nb++) {
                mma_f16(S[nb], aH, bh[nb]);
                mma_f16(S[nb], aH, bl[nb]);
            }
        }
        #pragma unroll
        for (int nb = 0; nb < 8; nb++)
            #pragma unroll
            for (int q = 0; q < 4; q++) S[nb][q] *= 0.125f;

        // ---- online softmax ----
        float mx0 = -1e30f, mx1 = -1e30f;
        #pragma unroll
        for (int nb = 0; nb < 8; nb++) {
            mx0 = fmaxf(mx0, fmaxf(S[nb][0], S[nb][1]));
            mx1 = fmaxf(mx1, fmaxf(S[nb][2], S[nb][3]));
        }
        mx0 = fmaxf(mx0, __shfl_xor_sync(0xffffffffu, mx0, 1));
        mx0 = fmaxf(mx0, __shfl_xor_sync(0xffffffffu, mx0, 2));
        mx1 = fmaxf(mx1, __shfl_xor_sync(0xffffffffu, mx1, 1));
        mx1 = fmaxf(mx1, __shfl_xor_sync(0xffffffffu, mx1, 2));
        float nm0 = fmaxf(m0r, mx0), nm1 = fmaxf(m1r, mx1);
        float al0 = __expf(m0r - nm0), al1 = __expf(m1r - nm1);
        m0r = nm0; m1r = nm1;
        float sum0 = 0.f, sum1 = 0.f;
        #pragma unroll
        for (int nb = 0; nb < 8; nb++) {
            S[nb][0] = __expf(S[nb][0] - nm0); sum0 += S[nb][0];
            S[nb][1] = __expf(S[nb][1] - nm0); sum0 += S[nb][1];
            S[nb][2] = __expf(S[nb][2] - nm1); sum1 += S[nb][2];
            S[nb][3] = __expf(S[nb][3] - nm1); sum1 += S[nb][3];
        }
        sum0 += __shfl_xor_sync(0xffffffffu, sum0, 1);
        sum0 += __shfl_xor_sync(0xffffffffu, sum0, 2);
        sum1 += __shfl_xor_sync(0xffffffffu, sum1, 1);
        sum1 += __shfl_xor_sync(0xffffffffu, sum1, 2);
        l0r = l0r * al0 + sum0;
        l1r = l1r * al1 + sum1;
        #pragma unroll
        for (int nb = 0; nb < 8; nb++) {
            O[nb][0] *= al0; O[nb][1] *= al0;
            O[nb][2] *= al1; O[nb][3] *= al1;
        }

        // ---- O += P*V (2-term), P hi-only packed in-register ----
        #pragma unroll
        for (int kk = 0; kk < 4; kk++) {
            uint32_t ph[4];
            ph[0] = h2u(__halves2half2(__float2half(S[2*kk][0]),   __float2half(S[2*kk][1])));
            ph[1] = h2u(__halves2half2(__float2half(S[2*kk][2]),   __float2half(S[2*kk][3])));
            ph[2] = h2u(__halves2half2(__float2half(S[2*kk+1][0]), __float2half(S[2*kk+1][1])));
            ph[3] = h2u(__halves2half2(__float2half(S[2*kk+1][2]), __float2half(S[2*kk+1][3])));
            uint32_t bh[8][2], bl[8][2];
            #pragma unroll
            for (int pr = 0; pr < 4; pr++) {
                uint32_t boff = SWZ128((uint32_t)((pr * 16 + b_r) * 128 + (kk * 16 + b_k8) * 2));
                uint32_t r4[4];
                ldsm4(r4, sVh + boff);
                bh[pr * 2][0] = r4[0]; bh[pr * 2][1] = r4[1];
                bh[pr * 2 + 1][0] = r4[2]; bh[pr * 2 + 1][1] = r4[3];
                ldsm4(r4, sVl + boff);
                bl[pr * 2][0] = r4[0]; bl[pr * 2][1] = r4[1];
                bl[pr * 2 + 1][0] = r4[2]; bl[pr * 2 + 1][1] = r4[3];
            }
            #pragma unroll
            for (int nb = 0; nb < 8; nb++) {
                mma_f16(O[nb], ph, bh[nb]);
                mma_f16(O[nb], ph, bl[nb]);
            }
        }
    }

    // ---- epilogue: normalize, write fp16 hi ctx ----
    const float i0 = 1.f / l0r, i1 = 1.f / l1r;
    const int r0 = b * SEQ + qt * 64 + wid * 16 + (lane >> 2);
    const int c0 = hoff + 2 * (lane & 3);
    #pragma unroll
    for (int nb = 0; nb < 8; nb++) {
        const int col = c0 + nb * 8;
        *(__half2*)(ctx_h + (size_t)r0 * WDIM + col) =
            __halves2half2(__float2half(O[nb][0] * i0), __float2half(O[nb][1] * i0));
        *(__half2*)(ctx_h + (size_t)(r0 + 8) * WDIM + col) =
            __halves2half2(__float2half(O[nb][2] * i1), __float2half(O[nb][3] * i1));
    }
}

// ---------------------------------------------------------------------------
// Residual add + LayerNorm. SPLIT: 0 none, 1 fp16-hi out.
// ---------------------------------------------------------------------------
template<int SPLIT>
__global__ void __launch_bounds__(256) ln_residual(
    const float* __restrict__ x, const float* __restrict__ r,
    const float* __restrict__ gamma, const float* __restrict__ beta,
    float* __restrict__ out, uint16_t* __restrict__ oh)
{
    __shared__ float red[2][8];
    __shared__ float stats[2];
    const int row = blockIdx.x, tid = threadIdx.x;
    const size_t base = (size_t)row * WDIM;
    float v[4];
    float s = 0.f, sq = 0.f;
    #pragma unroll
    for (int c = 0; c < 4; c++) {
        int w = tid + c * 256;
        float a = x[base + w] + r[base + w];
        v[c] = a; s += a; sq += a * a;
    }
    #pragma unroll
    for (int off = 16; off; off >>= 1) {
        s  += __shfl_xor_sync(0xffffffffu, s, off);
        sq += __shfl_xor_sync(0xffffffffu, sq, off);
    }
    int lane = tid & 31, wid = tid >> 5;
    if (lane == 0) { red[0][wid] = s; red[1][wid] = sq; }
    __syncthreads();
    if (tid == 0) {
        float ts = 0.f, tq = 0.f;
        #pragma unroll
        for (int w = 0; w < 8; w++) { ts += red[0][w]; tq += red[1][w]; }
        float mean = ts * (1.f / WDIM);
        float var  = tq * (1.f / WDIM) - mean * mean;
        stats[0] = mean;
        stats[1] = rsqrtf(var + 1e-5f);
    }
    __syncthreads();
    float mean = stats[0], rstd = stats[1];
    #pragma unroll
    for (int c = 0; c < 4; c++) {
        int w = tid + c * 256;
        float o = (v[c] - mean) * rstd * gamma[w] + beta[w];
        out[base + w] = o;
        if (SPLIT) ((__half*)oh)[base + w] = __float2half(o);
    }
}

// ---------------------------------------------------------------------------
// Topic kernel (unchanged)
// ---------------------------------------------------------------------------
__global__ void __launch_bounds__(256) topic_kernel(
    const float* __restrict__ hidden, const int* __restrict__ in_ids,
    const int* __restrict__ res_ids, const float* __restrict__ tw,
    const float* __restrict__ tb, const float* __restrict__ tt,
    float* __restrict__ ue)
{
    __shared__ float mp[WDIM];
    __shared__ float logits[64];
    __shared__ float probs[64];
    __shared__ int sid[SEQ];
    const int tid = threadIdx.x;
    const int g = blockIdx.x, b = blockIdx.y;

    for (int s = tid; s < SEQ; s += 256) {
        int id;
        if (g < 6) id = (s < S_IN) ? in_ids[b * S_IN + s] : 0;
        else       id = (s >= S_IN) ? res_ids[b * 129 + (s - S_IN + 1)] : 0;
        sid[s] = id;
    }
    __syncthreads();

    const int gid = (g < 6) ? (g + 1) : 1;
    float acc[4] = {0.f, 0.f, 0.f, 0.f};
    for (int s = 0; s < SEQ; s++) {
        if (sid[s] == gid) {
            const float* hr = hidden + (size_t)(b * SEQ + s) * WDIM;
            #pragma unroll
            for (int c = 0; c < 4; c++)
                acc[c] = fmaxf(acc[c], hr[tid + c * 256]);
        }
    }
    #pragma unroll
    for (int c = 0; c < 4; c++) mp[tid + c * 256] = acc[c];
    __syncthreads();

    int lane = tid & 31, wid = tid >> 5;
    for (int t = wid; t < NTOP; t += 8) {
        const float* wrow = tw + (size_t)t * WDIM;
        float d = 0.f;
        for (int w = lane; w < WDIM; w += 32) d += mp[w] * wrow[w];
        #pragma unroll
        for (int off = 16; off; off >>= 1)
            d += __shfl_xor_sync(0xffffffffu, d, off);
        if (lane == 0) logits[t] = d + tb[t];
    }
    __syncthreads();

    if (tid < 32) {
        float mval = -1e30f;
        for (int t = tid; t < NTOP; t += 32) mval = fmaxf(mval, logits[t]);
        #pragma unroll
        for (int off = 16; off; off >>= 1)
            mval = fmaxf(mval, __shfl_xor_sync(0xffffffffu, mval, off));
        float ssum = 0.f;
        for (int t = tid; t < NTOP; t += 32) {
            float p = __expf(logits[t] - mval);
            probs[t] = p; ssum += p;
        }
        #pragma unroll
        for (int off = 16; off; off >>= 1)
            ssum += __shfl_xor_sync(0xffffffffu, ssum, off);
        float inv = 1.f / ssum;
        for (int t = tid; t < NTOP; t += 32) probs[t] *= inv;
    }
    __syncthreads();

    float uacc[4] = {0.f, 0.f, 0.f, 0.f};
    for (int t = 0; t < NTOP; t++) {
        float p = probs[t];
        const float* trow = tt + (size_t)t * WDIM;
        #pragma unroll
        for (int c = 0; c < 4; c++) uacc[c] += p * trow[tid + c * 256];
    }
    float* urow = ue + (size_t)(b * NGRP + g) * WDIM;
    #pragma unroll
    for (int c = 0; c < 4; c++) urow[tid + c * 256] = uacc[c];
}

// ---------------------------------------------------------------------------
// Final scatter-add (unchanged)
// ---------------------------------------------------------------------------
__global__ void __launch_bounds__(256) final_add(
    const float* __restrict__ inp, const int* __restrict__ in_ids,
    const int* __restrict__ res_ids, const float* __restrict__ ue,
    float* __restrict__ out)
{
    const int row = blockIdx.x, tid = threadIdx.x;
    const int b = row >> 9, s = row & 511;
    int g = 0; float mult = 0.f;
    if (s < S_IN) {
        int id = in_ids[b * S_IN + s];
        if (id > 0)      { g = id - 1;  mult = 1.f; }
        else if (id < 0) { g = -id - 1; mult = 2.f; }
    } else {
        int id = res_ids[b * 129 + (s - S_IN + 1)];
        g = 6;
        if (id > 0)      mult = 1.f;
        else if (id < 0) mult = 2.f;
    }
    const size_t base = (size_t)row * WDIM;
    const float* urow = ue + (size_t)(b * NGRP + g) * WDIM;
    #pragma unroll
    for (int c = 0; c < 4; c++) {
        int w = tid + c * 256;
        out[base + w] = inp[base + w] + mult * urow[w];
    }
}

// ---------------------------------------------------------------------------
// Launch
// ---------------------------------------------------------------------------
extern "C" void kernel_launch(void* const* d_in, const int* in_sizes, int n_in,
                              void* d_out, int out_size)
{
    const float* inp     = (const float*)d_in[0];
    const int*   in_ids  = (const int*)  d_in[1];
    const int*   res_ids = (const int*)  d_in[2];
    const float* Wqkv    = (const float*)d_in[3];
    const float* bqkv    = (const float*)d_in[4];
    const float* Wo      = (const float*)d_in[5];
    const float* bo      = (const float*)d_in[6];
    const float* ln1g    = (const float*)d_in[7];
    const float* ln1b    = (const float*)d_in[8];
    const float* W1      = (const float*)d_in[9];
    const float* b1      = (const float*)d_in[10];
    const float* W2      = (const float*)d_in[11];
    const float* b2      = (const float*)d_in[12];
    const float* ln2g    = (const float*)d_in[13];
    const float* ln2b    = (const float*)d_in[14];
    const float* tw      = (const float*)d_in[15];
    const float* tb      = (const float*)d_in[16];
    const float* tt      = (const float*)d_in[17];
    float* out = (float*)d_out;

    float *tmp, *y, *hidden, *ue;
    cudaGetSymbolAddress((void**)&tmp,    g_tmp);
    cudaGetSymbolAddress((void**)&y,      g_y);
    cudaGetSymbolAddress((void**)&hidden, g_hidden);
    cudaGetSymbolAddress((void**)&ue,     g_ue);

    uint16_t *qkv_h, *qkv_l, *inp_h, *ctx_h, *yh, *ffh;
    uint16_t *wqkv_h, *wqkv_l, *wo_h, *wo_l, *w1_h, *w1_l, *w2_h, *w2_l;
    cudaGetSymbolAddress((void**)&qkv_h,  g_qkv_h);
    cudaGetSymbolAddress((void**)&qkv_l,  g_qkv_l);
    cudaGetSymbolAddress((void**)&inp_h,  g_inp_h);
    cudaGetSymbolAddress((void**)&ctx_h,  g_ctx_h);
    cudaGetSymbolAddress((void**)&yh,     g_yh);
    cudaGetSymbolAddress((void**)&ffh,    g_ffh);
    cudaGetSymbolAddress((void**)&wqkv_h, g_wqkv_h);
    cudaGetSymbolAddress((void**)&wqkv_l, g_wqkv_l);
    cudaGetSymbolAddress((void**)&wo_h,   g_wo_h);
    cudaGetSymbolAddress((void**)&wo_l,   g_wo_l);
    cudaGetSymbolAddress((void**)&w1_h,   g_w1_h);
    cudaGetSymbolAddress((void**)&w1_l,   g_w1_l);
    cudaGetSymbolAddress((void**)&w2_h,   g_w2_h);
    cudaGetSymbolAddress((void**)&w2_l,   g_w2_l);

    cudaFuncSetAttribute(attn_flash,
                         cudaFuncAttributeMaxDynamicSharedMemorySize, ATT_SMEM);
    cudaFuncSetAttribute(gemm_mma<0,0>,
                         cudaFuncAttributeMaxDynamicSharedMemorySize, GEMM_SMEM);
    cudaFuncSetAttribute(gemm_mma<0,2>,
                         cudaFuncAttributeMaxDynamicSharedMemorySize, GEMM_SMEM);
    cudaFuncSetAttribute(gemm_mma<1,1>,
                         cudaFuncAttributeMaxDynamicSharedMemorySize, GEMM_SMEM);

    // 0) fp32 -> fp16 splits: input hi-only, weights hi+lo
    auto split_hi = [&](const float* s, uint16_t* h, size_t n) {
        int n4 = (int)(n / 4);
        split_f32h<0><<<(n4 + 255) / 256, 256>>>(s, h, nullptr, n4);
    };
    auto split_hl = [&](const float* s, uint16_t* h, uint16_t* l, size_t n) {
        int n4 = (int)(n / 4);
        split_f32h<1><<<(n4 + 255) / 256, 256>>>(s, h, l, n4);
    };
    split_hi(inp,  inp_h,  (size_t)MTOT * WDIM);
    split_hl(Wqkv, wqkv_h, wqkv_l, (size_t)3 * WDIM * WDIM);
    split_hl(Wo,   wo_h,   wo_l,   (size_t)WDIM * WDIM);
    split_hl(W1,   w1_h,   w1_l,   (size_t)DFFDIM * WDIM);
    split_hl(W2,   w2_h,   w2_l,   (size_t)WDIM * DFFDIM);

    // 1) QKV projection (fp16 2-term) -> qkv hi+lo fp16
    gemm_mma<0,2><<<dim3(3 * WDIM / 128, MTOT / 128), 256, GEMM_SMEM>>>(
        inp_h, wqkv_h, wqkv_l, bqkv, nullptr, qkv_h, qkv_l, 3 * WDIM, WDIM);
    // 2) Attention (fp16 2-term tensor) -> ctx hi
    attn_flash<<<dim3(SEQ / 64, HEADS, BATCH), 128, ATT_SMEM>>>(qkv_h, qkv_l, ctx_h);
    // 3) O projection (fp16 2-term): tmp = ctx @ Wo^T + bo
    gemm_mma<0,0><<<dim3(WDIM / 128, MTOT / 128), 256, GEMM_SMEM>>>(
        ctx_h, wo_h, wo_l, bo, tmp, nullptr, nullptr, WDIM, WDIM);
    // 4) LN1(inp + tmp) -> y (fp32) + yh (fp16)
    ln_residual<1><<<MTOT, 256>>>(inp, tmp, ln1g, ln1b, y, yh);
    // 5) FF1 + GELU (fp16 2-term): ffh = gelu(y @ W1^T + b1)
    gemm_mma<1,1><<<dim3(DFFDIM / 128, MTOT / 128), 256, GEMM_SMEM>>>(
        yh, w1_h, w1_l, b1, nullptr, ffh, nullptr, DFFDIM, WDIM);
    // 6) FF2 (fp16 2-term): tmp = ff @ W2^T + b2
    gemm_mma<0,0><<<dim3(WDIM / 128, MTOT / 128), 256, GEMM_SMEM>>>(
        ffh, w2_h, w2_l, b2, tmp, nullptr, nullptr, WDIM, DFFDIM);
    // 7) LN2(y + tmp) -> hidden
    ln_residual<0><<<MTOT, 256>>>(y, tmp, ln2g, ln2b, hidden, nullptr);
    // 8) Topic embeddings
    topic_kernel<<<dim3(NGRP, BATCH), 256>>>(hidden, in_ids, res_ids, tw, tb, tt, ue);
    // 9) Final scatter-add
    final_add<<<MTOT, 256>>>(inp, in_ids, res_ids, ue, out);
}